// round 6
// baseline (speedup 1.0000x reference)
#include <cuda_runtime.h>
#include <cuda_bf16.h>
#include <stdint.h>

// ---------------------------------------------------------------------------
// SeqFCEncoder via warp-level mma.sync (compute_103 base ISA).
// Split-bf16 3-pass per GEMM: A*B = Ahi*Bhi + Alo*Bhi + Ahi*Blo (fp32 accum).
// R6: merged MMA regions — GEMM2(kc) + GEMM1(kc+1) run back-to-back with no
//     barrier between them (240 MMAs per region); convert isolated between
//     two bars with register-resident inputs; parallel threefry prologue.
// ---------------------------------------------------------------------------

typedef unsigned int u32;
typedef unsigned long long u64;

#define B_TOTAL   262144
#define LSEQ      50
#define HDIM      1024
#define EDIM      256
#define MTILE     128
#define NTHREADS  512
#define KC        64
#define NCHUNK    (HDIM / KC)     // 16
#define K1PAD     64

// ---- smem layout (bytes, dynamic) ----
#define SM_XHI   0               // 16KB  X hi  [128 m][64 k] SW128
#define SM_XLO   16384           // 16KB
#define SM_HHI   32768           // 16KB  h chunk hi (also fp32 x staging early)
#define SM_HLO   49152           // 16KB
#define SM_W1    65536           // 2 x 16KB double buffer [hi 8K | lo 8K]
#define W1BUFSZ  16384
#define SM_W2    98304           // 2 x 64KB double buffer [hi 32K | lo 32K]
#define W2BUFSZ  65536
#define SM_B2    229376          // 1KB
#define SMEM_TOTAL 230400

// ---- pre-split, pre-swizzled weight images (SW128 K-major [n][k=64]) ----
__device__ __align__(1024) unsigned char g_w1img[NCHUNK][2][KC   * K1PAD * 2]; // 256KB
__device__ __align__(1024) unsigned char g_w2img[NCHUNK][2][EDIM * K1PAD * 2]; // 1MB

// ============================ low-level helpers =============================
__device__ __forceinline__ u32 smem_u32_of(const void* p) {
  u32 a;
  asm("{ .reg .u64 t; cvta.to.shared.u64 t, %1; cvt.u32.u64 %0, t; }" : "=r"(a) : "l"(p));
  return a;
}
__device__ __forceinline__ u32 swz(int r, int k) {
  u32 off = ((u32)(r >> 3) << 10) | ((u32)(r & 7) << 7) | ((u32)k << 1);
  return off ^ ((off >> 3) & 0x70u);
}
__device__ __forceinline__ void ldsm4(u32 addr, u32 f[4]) {
  asm volatile("ldmatrix.sync.aligned.m8n8.x4.shared.b16 {%0,%1,%2,%3}, [%4];"
               : "=r"(f[0]), "=r"(f[1]), "=r"(f[2]), "=r"(f[3]) : "r"(addr));
}
__device__ __forceinline__ u32 a_addr(u32 img, int m0, int k0, int lr, int lg) {
  return img + swz(m0 + lr + ((lg & 1) << 3), k0 + ((lg >> 1) << 3));
}
__device__ __forceinline__ u32 b_addr(u32 img, int n0, int k0, int lr, int lg) {
  return img + swz(n0 + lr + ((lg >> 1) << 3), k0 + ((lg & 1) << 3));
}
__device__ __forceinline__ void mma16816(float c[4], const u32 a[4], u32 b0, u32 b1) {
  asm volatile(
    "mma.sync.aligned.m16n8k16.row.col.f32.bf16.bf16.f32 "
    "{%0,%1,%2,%3}, {%4,%5,%6,%7}, {%8,%9}, {%0,%1,%2,%3};"
    : "+f"(c[0]), "+f"(c[1]), "+f"(c[2]), "+f"(c[3])
    : "r"(a[0]), "r"(a[1]), "r"(a[2]), "r"(a[3]), "r"(b0), "r"(b1));
}
__device__ __forceinline__ void cpa16(u32 dst, const void* src) {
  asm volatile("cp.async.cg.shared.global [%0], [%1], 16;" :: "r"(dst), "l"(src));
}
#define CP_COMMIT() asm volatile("cp.async.commit_group;" ::: "memory")
#define CP_WAIT0()  asm volatile("cp.async.wait_group 0;" ::: "memory")
#define CP_WAIT1()  asm volatile("cp.async.wait_group 1;" ::: "memory")

// ============================ threefry dropout ==============================
__device__ __forceinline__ u32 rotl32(u32 x, u32 r) { return __funnelshift_l(x, x, r); }
__device__ __forceinline__ void tf2x32(u32 x0, u32 x1, u32 &o0, u32 &o1) {
  const u32 ks0 = 0u, ks1 = 42u, ks2 = 0u ^ 42u ^ 0x1BD11BDAu;
  x0 += ks0; x1 += ks1;
#define TFR(r) { x0 += x1; x1 = rotl32(x1, r); x1 ^= x0; }
  TFR(13) TFR(15) TFR(26) TFR(6)
  x0 += ks1; x1 += ks2 + 1u;
  TFR(17) TFR(29) TFR(16) TFR(24)
  x0 += ks2; x1 += ks0 + 2u;
  TFR(13) TFR(15) TFR(26) TFR(6)
  x0 += ks0; x1 += ks1 + 3u;
  TFR(17) TFR(29) TFR(16) TFR(24)
  x0 += ks1; x1 += ks2 + 4u;
  TFR(13) TFR(15) TFR(26) TFR(6)
  x0 += ks2; x1 += ks0 + 5u;
#undef TFR
  o0 = x0; o1 = x1;
}
__device__ __forceinline__ bool drop_elem(u32 i) {   // validated rel_err 0.0 (R1)
  u32 o0, o1;
  tf2x32(0u, i, o0, o1);
  u32 bits = o0 ^ o1;
  float u = __uint_as_float((bits >> 9) | 0x3f800000u) - 1.0f;
  return u < 0.2f;
}

// ============================ split helpers =================================
__device__ __forceinline__ void split_pack(float a, float b, u32 &h, u32 &l) {
  __nv_bfloat16 ha = __float2bfloat16(a);
  __nv_bfloat16 hb = __float2bfloat16(b);
  __nv_bfloat16 la = __float2bfloat16(a - __bfloat162float(ha));
  __nv_bfloat16 lb = __float2bfloat16(b - __bfloat162float(hb));
  h = (u32)__bfloat16_as_ushort(ha) | ((u32)__bfloat16_as_ushort(hb) << 16);
  l = (u32)__bfloat16_as_ushort(la) | ((u32)__bfloat16_as_ushort(lb) << 16);
}

// ============================ prep kernel ===================================
__global__ void prep_kernel(const float* __restrict__ W1,
                            const float* __restrict__ W2) {
  int idx = blockIdx.x * blockDim.x + threadIdx.x;
  const int N1 = NCHUNK * KC * K1PAD;
  const int N2 = NCHUNK * EDIM * K1PAD;
  if (idx < N1) {
    int kc = idx / (KC * K1PAD);
    int r  = idx - kc * (KC * K1PAD);
    int n = r / K1PAD, k = r - (r / K1PAD) * K1PAD;
    float w = (k < LSEQ) ? W1[(size_t)k * HDIM + kc * KC + n] : 0.0f;
    __nv_bfloat16 hi = __float2bfloat16(w);
    __nv_bfloat16 lo = __float2bfloat16(w - __bfloat162float(hi));
    u32 sw = swz(n, k);
    *(unsigned short*)&g_w1img[kc][0][sw] = __bfloat16_as_ushort(hi);
    *(unsigned short*)&g_w1img[kc][1][sw] = __bfloat16_as_ushort(lo);
  } else if (idx < N1 + N2) {
    int r2 = idx - N1;
    int kc = r2 / (EDIM * K1PAD);
    int r  = r2 - kc * (EDIM * K1PAD);
    int n = r / K1PAD, k = r - (r / K1PAD) * K1PAD;
    float w = W2[(size_t)(kc * KC + k) * EDIM + n];
    __nv_bfloat16 hi = __float2bfloat16(w);
    __nv_bfloat16 lo = __float2bfloat16(w - __bfloat162float(hi));
    u32 sw = swz(n, k);
    *(unsigned short*)&g_w2img[kc][0][sw] = __bfloat16_as_ushort(hi);
    *(unsigned short*)&g_w2img[kc][1][sw] = __bfloat16_as_ushort(lo);
  }
}

// ============================ main kernel ===================================
extern __shared__ __align__(1024) unsigned char smem_raw[];

// GEMM1 for one KC-chunk: acc1 = X @ W1chunk (warp tile 32 x 16), 48 MMAs
__device__ __forceinline__ void gemm1_block(
    const unsigned char* smem_raw_, u32 sm, u32 w1b,
    int wr, int wc, int lr, int lg, float acc1[2][2][4])
{
#pragma unroll
  for (int mt = 0; mt < 2; ++mt)
#pragma unroll
    for (int j = 0; j < 2; ++j)
#pragma unroll
      for (int q = 0; q < 4; ++q) acc1[mt][j][q] = 0.0f;
#pragma unroll
  for (int kt = 0; kt < 4; ++kt) {
    const int k0 = kt * 16;
    u32 axh[2][4], axl[2][4];
    ldsm4(a_addr(sm + SM_XHI, wr * 32,      k0, lr, lg), axh[0]);
    ldsm4(a_addr(sm + SM_XHI, wr * 32 + 16, k0, lr, lg), axh[1]);
    ldsm4(a_addr(sm + SM_XLO, wr * 32,      k0, lr, lg), axl[0]);
    ldsm4(a_addr(sm + SM_XLO, wr * 32 + 16, k0, lr, lg), axl[1]);
    u32 bh[4], bl[4];
    const int n0 = wc * 16;
    ldsm4(b_addr(w1b,         n0, k0, lr, lg), bh);
    ldsm4(b_addr(w1b + 8192u, n0, k0, lr, lg), bl);
    mma16816(acc1[0][0], axh[0], bh[0], bh[1]);
    mma16816(acc1[0][1], axh[0], bh[2], bh[3]);
    mma16816(acc1[1][0], axh[1], bh[0], bh[1]);
    mma16816(acc1[1][1], axh[1], bh[2], bh[3]);
    mma16816(acc1[0][0], axl[0], bh[0], bh[1]);
    mma16816(acc1[0][1], axl[0], bh[2], bh[3]);
    mma16816(acc1[1][0], axl[1], bh[0], bh[1]);
    mma16816(acc1[1][1], axl[1], bh[2], bh[3]);
    mma16816(acc1[0][0], axh[0], bl[0], bl[1]);
    mma16816(acc1[0][1], axh[0], bl[2], bl[3]);
    mma16816(acc1[1][0], axh[1], bl[0], bl[1]);
    mma16816(acc1[1][1], axh[1], bl[2], bl[3]);
  }
}

// convert acc1 (+bias, relu) -> h images (bias values pre-loaded in bv[4])
__device__ __forceinline__ void convert_block(
    unsigned char* smem_raw_, const float acc1[2][2][4], const float bv[4],
    int wr, int wc, int gid, int tig)
{
#pragma unroll
  for (int mt = 0; mt < 2; ++mt) {
    const int r0 = wr * 32 + mt * 16 + gid;
#pragma unroll
    for (int j = 0; j < 2; ++j) {
      const int cc = wc * 16 + j * 8 + 2 * tig;
      const float bb0 = bv[j * 2], bb1 = bv[j * 2 + 1];
      float v0 = fmaxf(acc1[mt][j][0] + bb0, 0.0f);
      float v1 = fmaxf(acc1[mt][j][1] + bb1, 0.0f);
      float v2 = fmaxf(acc1[mt][j][2] + bb0, 0.0f);
      float v3 = fmaxf(acc1[mt][j][3] + bb1, 0.0f);
      u32 h0, l0, h1, l1;
      split_pack(v0, v1, h0, l0);
      split_pack(v2, v3, h1, l1);
      u32 oa = swz(r0, cc), ob = swz(r0 + 8, cc);
      *(u32*)(smem_raw_ + SM_HHI + oa) = h0;
      *(u32*)(smem_raw_ + SM_HLO + oa) = l0;
      *(u32*)(smem_raw_ + SM_HHI + ob) = h1;
      *(u32*)(smem_raw_ + SM_HLO + ob) = l1;
    }
  }
}

__global__ void __launch_bounds__(NTHREADS, 1)
seqfc_main(const float* __restrict__ seq,
           const float* __restrict__ b1,
           const float* __restrict__ b2,
           float* __restrict__ out)
{
  const int tid  = threadIdx.x;
  const int wid  = tid >> 5;
  const int lane = tid & 31;
  const int lr   = lane & 7;
  const int lg   = lane >> 3;
  const int gid  = lane >> 2;
  const int tig  = lane & 3;
  const int wr   = wid >> 2;          // 4 row groups of 32 rows
  const int wc   = wid & 3;           // 4 col groups
  const int row0 = blockIdx.x * MTILE;

  const u32 sm = smem_u32_of(smem_raw);
  float* b2s = (float*)(smem_raw + SM_B2);

  // ---- prologue cp group: W1[0] -> buf0, W1[1] -> buf1, W2[0] -> buf0 ----
  {
    const unsigned char* s10 = &g_w1img[0][0][0];
    const unsigned char* s11 = &g_w1img[1][0][0];
    const unsigned char* s2  = &g_w2img[0][0][0];
    for (int i = tid; i < 1024; i += NTHREADS) {
      cpa16(sm + SM_W1 + i * 16,            s10 + (size_t)i * 16);
      cpa16(sm + SM_W1 + W1BUFSZ + i * 16,  s11 + (size_t)i * 16);
    }
    for (int i = tid; i < 4096; i += NTHREADS)
      cpa16(sm + SM_W2 + i * 16, s2 + (size_t)i * 16);
    CP_COMMIT();
  }
  for (int i = tid; i < EDIM; i += NTHREADS) b2s[i] = b2[i];

  // ---- X stage (all 512 threads; 4 threads per row) ----
  {
    float* xs = (float*)(smem_raw + SM_HHI);       // fp32 staging, stride 52
    const float* sp = seq + (size_t)row0 * LSEQ;
    for (int idx = tid; idx < MTILE * LSEQ; idx += NTHREADS) {
      int r = idx / LSEQ, k = idx - r * LSEQ;
      xs[r * 52 + k] = sp[idx];
    }
    __syncthreads();

    const int xrow = tid >> 2;
    const int q    = tid & 3;
    float xv[16];
#pragma unroll
    for (int i = 0; i < 16; ++i) {
      int k = q * 16 + i;
      xv[i] = (k < LSEQ) ? xs[xrow * 52 + k] : 0.0f;
    }
    int f = LSEQ;
#pragma unroll
    for (int i = 15; i >= 0; --i) {
      int k = q * 16 + i;
      if (k < LSEQ && xv[i] == -1.0f) f = k;
    }
    f = min(f, __shfl_xor_sync(0xffffffffu, f, 1));
    f = min(f, __shfl_xor_sync(0xffffffffu, f, 2));
    const u32 gb = (u32)(row0 + xrow) * (u32)LSEQ;
#pragma unroll
    for (int i = 0; i < 16; ++i) {
      int k = q * 16 + i;
      if (k < f && drop_elem(gb + (u32)k)) xv[i] = 0.0f;
    }
    __syncthreads();          // staging reads done before image writes reuse? (disjoint regions: X images separate; sync guards xs reuse as h later anyway)
#pragma unroll
    for (int c = 0; c < 8; ++c) {
      u32 h, l;
      split_pack(xv[2 * c], xv[2 * c + 1], h, l);
      u32 o = swz(xrow, q * 16 + 2 * c);
      *(u32*)(smem_raw + SM_XHI + o) = h;
      *(u32*)(smem_raw + SM_XLO + o) = l;
    }
  }

  CP_WAIT0();
  __syncthreads();            // X images + W1[0]/W1[1]/W2[0] ready

  // ---- prologue pipeline stage: GEMM1(0) + convert(0) ----
  {
    float bv[4];
#pragma unroll
    for (int j = 0; j < 2; ++j) {
      int cc = wc * 16 + j * 8 + 2 * tig;
      bv[j * 2]     = __ldg(b1 + cc);
      bv[j * 2 + 1] = __ldg(b1 + cc + 1);
    }
    float acc1[2][2][4];
    gemm1_block(smem_raw, sm, sm + SM_W1, wr, wc, lr, lg, acc1);
    convert_block(smem_raw, acc1, bv, wr, wc, gid, tig);
  }
  __syncthreads();            // h[0] visible

  // ---- GEMM2 accumulators: warp tile = 32 rows x 64 cols ----
  float acc2[2][8][4];
#pragma unroll
  for (int mt = 0; mt < 2; ++mt)
#pragma unroll
    for (int j = 0; j < 8; ++j)
#pragma unroll
      for (int q = 0; q < 4; ++q) acc2[mt][j][q] = 0.0f;

  // ---- chunk loop ----
  for (int kc = 0; kc < NCHUNK; ++kc) {
    // (1) prefetch group: W1[kc+2] -> buf kc&1, W2[kc+1] -> buf (kc+1)&1
    if (kc + 2 < NCHUNK) {
      const unsigned char* s1 = &g_w1img[kc + 2][0][0];
      u32 d1 = sm + SM_W1 + (u32)(kc & 1) * W1BUFSZ;
      for (int i = tid; i < 1024; i += NTHREADS) cpa16(d1 + i * 16, s1 + (size_t)i * 16);
    }
    if (kc + 1 < NCHUNK) {
      const unsigned char* s2 = &g_w2img[kc + 1][0][0];
      u32 d2 = sm + SM_W2 + (u32)((kc + 1) & 1) * W2BUFSZ;
      for (int i = tid; i < 4096; i += NTHREADS) cpa16(d2 + i * 16, s2 + (size_t)i * 16);
    }
    CP_COMMIT();
    CP_WAIT1();               // group from chunk kc-1 (W2[kc], W1[kc+1]) done

    // (2) bias prefetch for convert(kc+1)
    float bv[4];
    if (kc + 1 < NCHUNK) {
      const int bb = (kc + 1) * KC;
#pragma unroll
      for (int j = 0; j < 2; ++j) {
        int cc = bb + wc * 16 + j * 8 + 2 * tig;
        bv[j * 2]     = __ldg(b1 + cc);
        bv[j * 2 + 1] = __ldg(b1 + cc + 1);
      }
    }

    // (3) merged MMA region: GEMM2(kc) [192] then GEMM1(kc+1) [48]
    const u32 wb2 = sm + SM_W2 + (u32)(kc & 1) * W2BUFSZ;
#pragma unroll
    for (int kt = 0; kt < 4; ++kt) {
      const int k0 = kt * 16;
      u32 ahh[2][4], ahl[2][4];
      ldsm4(a_addr(sm + SM_HHI, wr * 32,      k0, lr, lg), ahh[0]);
      ldsm4(a_addr(sm + SM_HHI, wr * 32 + 16, k0, lr, lg), ahh[1]);
      ldsm4(a_addr(sm + SM_HLO, wr * 32,      k0, lr, lg), ahl[0]);
      ldsm4(a_addr(sm + SM_HLO, wr * 32 + 16, k0, lr, lg), ahl[1]);
#pragma unroll
      for (int half = 0; half < 2; ++half) {
        u32 b2h[2][4], b2l[2][4];
#pragma unroll
        for (int t = 0; t < 2; ++t) {
          const int n0 = wc * 64 + (half * 2 + t) * 16;
          ldsm4(b_addr(wb2,          n0, k0, lr, lg), b2h[t]);
          ldsm4(b_addr(wb2 + 32768u, n0, k0, lr, lg), b2l[t]);
        }
        const int jb = half * 4;
#pragma unroll
        for (int t = 0; t < 2; ++t) {
          mma16816(acc2[0][jb + 2*t],     ahh[0], b2h[t][0], b2h[t][1]);
          mma16816(acc2[0][jb + 2*t + 1], ahh[0], b2h[t][2], b2h[t][3]);
          mma16816(acc2[1][jb + 2*t],     ahh[1], b2h[t][0], b2h[t][1]);
          mma16816(acc2[1][jb + 2*t + 1], ahh[1], b2h[t][2], b2h[t][3]);
        }
#pragma unroll
        for (int t = 0; t < 2; ++t) {
          mma16816(acc2[0][jb + 2*t],     ahl[0], b2h[t][0], b2h[t][1]);
          mma16816(acc2[0][jb + 2*t + 1], ahl[0], b2h[t][2], b2h[t][3]);
          mma16816(acc2[1][jb + 2*t],     ahl[1], b2h[t][0], b2h[t][1]);
          mma16816(acc2[1][jb + 2*t + 1], ahl[1], b2h[t][2], b2h[t][3]);
        }
#pragma unroll
        for (int t = 0; t < 2; ++t) {
          mma16816(acc2[0][jb + 2*t],     ahh[0], b2l[t][0], b2l[t][1]);
          mma16816(acc2[0][jb + 2*t + 1], ahh[0], b2l[t][2], b2l[t][3]);
          mma16816(acc2[1][jb + 2*t],     ahh[1], b2l[t][0], b2l[t][1]);
          mma16816(acc2[1][jb + 2*t + 1], ahh[1], b2l[t][2], b2l[t][3]);
        }
      }
    }

    if (kc + 1 < NCHUNK) {
      float acc1[2][2][4];
      gemm1_block(smem_raw, sm, sm + SM_W1 + (u32)((kc + 1) & 1) * W1BUFSZ,
                  wr, wc, lr, lg, acc1);
      __syncthreads();        // all h[kc] reads done
      convert_block(smem_raw, acc1, bv, wr, wc, gid, tig);
      __syncthreads();        // h[kc+1] visible
    }
  }

  // ---- epilogue: + b2, store ----
#pragma unroll
  for (int mt = 0; mt < 2; ++mt) {
    const int r0 = row0 + wr * 32 + mt * 16 + gid;
#pragma unroll
    for (int j = 0; j < 8; ++j) {
      const int c = wc * 64 + j * 8 + 2 * tig;
      const float bb0 = b2s[c], bb1 = b2s[c + 1];
      float2 va = make_float2(acc2[mt][j][0] + bb0, acc2[mt][j][1] + bb1);
      float2 vb = make_float2(acc2[mt][j][2] + bb0, acc2[mt][j][3] + bb1);
      *(float2*)(out + (size_t)r0 * EDIM + c)       = va;
      *(float2*)(out + (size_t)(r0 + 8) * EDIM + c) = vb;
    }
  }
}

// ============================ launch ========================================
extern "C" void kernel_launch(void* const* d_in, const int* in_sizes, int n_in,
                              void* d_out, int out_size) {
  (void)in_sizes; (void)n_in; (void)out_size;
  const float* seq = (const float*)d_in[0];
  const float* W1  = (const float*)d_in[1];
  const float* b1  = (const float*)d_in[2];
  const float* W2  = (const float*)d_in[3];
  const float* b2  = (const float*)d_in[4];

  cudaFuncSetAttribute(seqfc_main, cudaFuncAttributeMaxDynamicSharedMemorySize,
                       SMEM_TOTAL);

  const int prep_total = NCHUNK * KC * K1PAD + NCHUNK * EDIM * K1PAD;
  prep_kernel<<<(prep_total + 255) / 256, 256>>>(W1, W2);
  seqfc_main<<<B_TOTAL / MTILE, NTHREADS, SMEM_TOTAL>>>(seq, b1, b2, (float*)d_out);
}

// round 7
// speedup vs baseline: 1.0806x; 1.0806x over previous
#include <cuda_runtime.h>
#include <cuda_bf16.h>
#include <stdint.h>

// ---------------------------------------------------------------------------
// SeqFCEncoder via warp-level mma.sync (compute_103 base ISA).
// Split-bf16 3-pass per GEMM: A*B = Ahi*Bhi + Alo*Bhi + Ahi*Blo (fp32 accum).
// R7: 2 CTAs/SM. MTILE=64, 256 threads, smem 112KB (single-buffered weights;
//     sibling CTA hides copy waits and barrier stalls). Math identical to R4-6.
// ---------------------------------------------------------------------------

typedef unsigned int u32;
typedef unsigned long long u64;

#define B_TOTAL   262144
#define LSEQ      50
#define HDIM      1024
#define EDIM      256
#define MTILE     64
#define NTHREADS  256
#define KC        64
#define NCHUNK    (HDIM / KC)     // 16
#define K1PAD     64

// ---- smem layout (bytes, dynamic) ----
#define SM_XHI   0               // 8KB  X hi  [64 m][64 k] SW128
#define SM_XLO   8192            // 8KB
#define SM_HHI   16384           // 8KB  h chunk hi (fp32 x staging early)
#define SM_HLO   24576           // 8KB
#define SM_W1    32768           // 16KB single buffer [hi 8K | lo 8K]
#define SM_W2    49152           // 64KB single buffer [hi 32K | lo 32K]
#define SMEM_TOTAL 114688        // 112KB -> 2 CTAs/SM

// ---- pre-split, pre-swizzled weight images (SW128 K-major [n][k=64]) ----
__device__ __align__(1024) unsigned char g_w1img[NCHUNK][2][KC   * K1PAD * 2]; // 256KB
__device__ __align__(1024) unsigned char g_w2img[NCHUNK][2][EDIM * K1PAD * 2]; // 1MB

// ============================ low-level helpers =============================
__device__ __forceinline__ u32 smem_u32_of(const void* p) {
  u32 a;
  asm("{ .reg .u64 t; cvta.to.shared.u64 t, %1; cvt.u32.u64 %0, t; }" : "=r"(a) : "l"(p));
  return a;
}
__device__ __forceinline__ u32 swz(int r, int k) {
  u32 off = ((u32)(r >> 3) << 10) | ((u32)(r & 7) << 7) | ((u32)k << 1);
  return off ^ ((off >> 3) & 0x70u);
}
__device__ __forceinline__ void ldsm4(u32 addr, u32 f[4]) {
  asm volatile("ldmatrix.sync.aligned.m8n8.x4.shared.b16 {%0,%1,%2,%3}, [%4];"
               : "=r"(f[0]), "=r"(f[1]), "=r"(f[2]), "=r"(f[3]) : "r"(addr));
}
__device__ __forceinline__ u32 a_addr(u32 img, int m0, int k0, int lr, int lg) {
  return img + swz(m0 + lr + ((lg & 1) << 3), k0 + ((lg >> 1) << 3));
}
__device__ __forceinline__ u32 b_addr(u32 img, int n0, int k0, int lr, int lg) {
  return img + swz(n0 + lr + ((lg >> 1) << 3), k0 + ((lg & 1) << 3));
}
__device__ __forceinline__ void mma16816(float c[4], const u32 a[4], u32 b0, u32 b1) {
  asm volatile(
    "mma.sync.aligned.m16n8k16.row.col.f32.bf16.bf16.f32 "
    "{%0,%1,%2,%3}, {%4,%5,%6,%7}, {%8,%9}, {%0,%1,%2,%3};"
    : "+f"(c[0]), "+f"(c[1]), "+f"(c[2]), "+f"(c[3])
    : "r"(a[0]), "r"(a[1]), "r"(a[2]), "r"(a[3]), "r"(b0), "r"(b1));
}
__device__ __forceinline__ void cpa16(u32 dst, const void* src) {
  asm volatile("cp.async.cg.shared.global [%0], [%1], 16;" :: "r"(dst), "l"(src));
}
#define CP_COMMIT() asm volatile("cp.async.commit_group;" ::: "memory")
#define CP_WAIT0()  asm volatile("cp.async.wait_group 0;" ::: "memory")

// ============================ threefry dropout ==============================
__device__ __forceinline__ u32 rotl32(u32 x, u32 r) { return __funnelshift_l(x, x, r); }
__device__ __forceinline__ void tf2x32(u32 x0, u32 x1, u32 &o0, u32 &o1) {
  const u32 ks0 = 0u, ks1 = 42u, ks2 = 0u ^ 42u ^ 0x1BD11BDAu;
  x0 += ks0; x1 += ks1;
#define TFR(r) { x0 += x1; x1 = rotl32(x1, r); x1 ^= x0; }
  TFR(13) TFR(15) TFR(26) TFR(6)
  x0 += ks1; x1 += ks2 + 1u;
  TFR(17) TFR(29) TFR(16) TFR(24)
  x0 += ks2; x1 += ks0 + 2u;
  TFR(13) TFR(15) TFR(26) TFR(6)
  x0 += ks0; x1 += ks1 + 3u;
  TFR(17) TFR(29) TFR(16) TFR(24)
  x0 += ks1; x1 += ks2 + 4u;
  TFR(13) TFR(15) TFR(26) TFR(6)
  x0 += ks2; x1 += ks0 + 5u;
#undef TFR
  o0 = x0; o1 = x1;
}
__device__ __forceinline__ bool drop_elem(u32 i) {   // validated rel_err 0.0 (R1)
  u32 o0, o1;
  tf2x32(0u, i, o0, o1);
  u32 bits = o0 ^ o1;
  float u = __uint_as_float((bits >> 9) | 0x3f800000u) - 1.0f;
  return u < 0.2f;
}

// ============================ split helpers =================================
__device__ __forceinline__ void split_pack(float a, float b, u32 &h, u32 &l) {
  __nv_bfloat16 ha = __float2bfloat16(a);
  __nv_bfloat16 hb = __float2bfloat16(b);
  __nv_bfloat16 la = __float2bfloat16(a - __bfloat162float(ha));
  __nv_bfloat16 lb = __float2bfloat16(b - __bfloat162float(hb));
  h = (u32)__bfloat16_as_ushort(ha) | ((u32)__bfloat16_as_ushort(hb) << 16);
  l = (u32)__bfloat16_as_ushort(la) | ((u32)__bfloat16_as_ushort(lb) << 16);
}

// ============================ prep kernel ===================================
__global__ void prep_kernel(const float* __restrict__ W1,
                            const float* __restrict__ W2) {
  int idx = blockIdx.x * blockDim.x + threadIdx.x;
  const int N1 = NCHUNK * KC * K1PAD;
  const int N2 = NCHUNK * EDIM * K1PAD;
  if (idx < N1) {
    int kc = idx / (KC * K1PAD);
    int r  = idx - kc * (KC * K1PAD);
    int n = r / K1PAD, k = r - (r / K1PAD) * K1PAD;
    float w = (k < LSEQ) ? W1[(size_t)k * HDIM + kc * KC + n] : 0.0f;
    __nv_bfloat16 hi = __float2bfloat16(w);
    __nv_bfloat16 lo = __float2bfloat16(w - __bfloat162float(hi));
    u32 sw = swz(n, k);
    *(unsigned short*)&g_w1img[kc][0][sw] = __bfloat16_as_ushort(hi);
    *(unsigned short*)&g_w1img[kc][1][sw] = __bfloat16_as_ushort(lo);
  } else if (idx < N1 + N2) {
    int r2 = idx - N1;
    int kc = r2 / (EDIM * K1PAD);
    int r  = r2 - kc * (EDIM * K1PAD);
    int n = r / K1PAD, k = r - (r / K1PAD) * K1PAD;
    float w = W2[(size_t)(kc * KC + k) * EDIM + n];
    __nv_bfloat16 hi = __float2bfloat16(w);
    __nv_bfloat16 lo = __float2bfloat16(w - __bfloat162float(hi));
    u32 sw = swz(n, k);
    *(unsigned short*)&g_w2img[kc][0][sw] = __bfloat16_as_ushort(hi);
    *(unsigned short*)&g_w2img[kc][1][sw] = __bfloat16_as_ushort(lo);
  }
}

// ============================ main kernel ===================================
extern __shared__ __align__(1024) unsigned char smem_raw[];

__global__ void __launch_bounds__(NTHREADS, 2)
seqfc_main(const float* __restrict__ seq,
           const float* __restrict__ b1,
           const float* __restrict__ b2,
           float* __restrict__ out)
{
  const int tid  = threadIdx.x;
  const int wid  = tid >> 5;
  const int lane = tid & 31;
  const int lr   = lane & 7;
  const int lg   = lane >> 3;
  const int gid  = lane >> 2;
  const int tig  = lane & 3;
  const int wr   = wid >> 2;          // 2 row groups of 32 rows
  const int wc   = wid & 3;           // 4 col groups
  const int row0 = blockIdx.x * MTILE;

  const u32 sm = smem_u32_of(smem_raw);

  // ---- X stage (all 256 threads; 4 threads per row) ----
  {
    float* xs = (float*)(smem_raw + SM_HHI);       // fp32 staging, stride 52
    const float* sp = seq + (size_t)row0 * LSEQ;
    for (int idx = tid; idx < MTILE * LSEQ; idx += NTHREADS) {
      int r = idx / LSEQ, k = idx - r * LSEQ;
      xs[r * 52 + k] = sp[idx];
    }
    __syncthreads();

    const int xrow = tid >> 2;
    const int q    = tid & 3;
    float xv[16];
#pragma unroll
    for (int i = 0; i < 16; ++i) {
      int k = q * 16 + i;
      xv[i] = (k < LSEQ) ? xs[xrow * 52 + k] : 0.0f;
    }
    int f = LSEQ;
#pragma unroll
    for (int i = 15; i >= 0; --i) {
      int k = q * 16 + i;
      if (k < LSEQ && xv[i] == -1.0f) f = k;
    }
    f = min(f, __shfl_xor_sync(0xffffffffu, f, 1));
    f = min(f, __shfl_xor_sync(0xffffffffu, f, 2));
    const u32 gb = (u32)(row0 + xrow) * (u32)LSEQ;
#pragma unroll
    for (int i = 0; i < 16; ++i) {
      int k = q * 16 + i;
      if (k < f && drop_elem(gb + (u32)k)) xv[i] = 0.0f;
    }
#pragma unroll
    for (int c = 0; c < 8; ++c) {
      u32 h, l;
      split_pack(xv[2 * c], xv[2 * c + 1], h, l);
      u32 o = swz(xrow, q * 16 + 2 * c);
      *(u32*)(smem_raw + SM_XHI + o) = h;
      *(u32*)(smem_raw + SM_XLO + o) = l;
    }
  }

  // ---- GEMM2 accumulators: warp tile = 32 rows x 64 cols ----
  float acc2[2][8][4];
#pragma unroll
  for (int mt = 0; mt < 2; ++mt)
#pragma unroll
    for (int j = 0; j < 8; ++j)
#pragma unroll
      for (int q = 0; q < 4; ++q) acc2[mt][j][q] = 0.0f;

  // ---- chunk loop (single-buffered weights; sibling CTA hides the waits) ----
  for (int kc = 0; kc < NCHUNK; ++kc) {
    __syncthreads();          // prior GEMM1/GEMM2 weight reads + xs staging done

    // issue W1[kc] + W2[kc] copies into the (now free) single buffers
    {
      const unsigned char* s1 = &g_w1img[kc][0][0];
      for (int i = tid; i < 1024; i += NTHREADS)
        cpa16(sm + SM_W1 + i * 16, s1 + (size_t)i * 16);
      const unsigned char* s2 = &g_w2img[kc][0][0];
      for (int i = tid; i < 4096; i += NTHREADS)
        cpa16(sm + SM_W2 + i * 16, s2 + (size_t)i * 16);
      CP_COMMIT();
    }

    // bias prefetch for this chunk's convert (L2/const cached)
    float bv[4];
    {
      const int bb = kc * KC;
#pragma unroll
      for (int j = 0; j < 2; ++j) {
        int cc = bb + wc * 16 + j * 8 + 2 * tig;
        bv[j * 2]     = __ldg(b1 + cc);
        bv[j * 2 + 1] = __ldg(b1 + cc + 1);
      }
    }

    CP_WAIT0();
    __syncthreads();          // weights visible to all warps

    // ---- GEMM1(kc): warp tile 32 x 16, 48 MMAs ----
    float acc1[2][2][4];
#pragma unroll
    for (int mt = 0; mt < 2; ++mt)
#pragma unroll
      for (int j = 0; j < 2; ++j)
#pragma unroll
        for (int q = 0; q < 4; ++q) acc1[mt][j][q] = 0.0f;

#pragma unroll
    for (int kt = 0; kt < 4; ++kt) {
      const int k0 = kt * 16;
      u32 axh[2][4], axl[2][4];
      ldsm4(a_addr(sm + SM_XHI, wr * 32,      k0, lr, lg), axh[0]);
      ldsm4(a_addr(sm + SM_XHI, wr * 32 + 16, k0, lr, lg), axh[1]);
      ldsm4(a_addr(sm + SM_XLO, wr * 32,      k0, lr, lg), axl[0]);
      ldsm4(a_addr(sm + SM_XLO, wr * 32 + 16, k0, lr, lg), axl[1]);
      u32 bh[4], bl[4];
      const int n0 = wc * 16;
      ldsm4(b_addr(sm + SM_W1,         n0, k0, lr, lg), bh);
      ldsm4(b_addr(sm + SM_W1 + 8192u, n0, k0, lr, lg), bl);
      mma16816(acc1[0][0], axh[0], bh[0], bh[1]);
      mma16816(acc1[0][1], axh[0], bh[2], bh[3]);
      mma16816(acc1[1][0], axh[1], bh[0], bh[1]);
      mma16816(acc1[1][1], axh[1], bh[2], bh[3]);
      mma16816(acc1[0][0], axl[0], bh[0], bh[1]);
      mma16816(acc1[0][1], axl[0], bh[2], bh[3]);
      mma16816(acc1[1][0], axl[1], bh[0], bh[1]);
      mma16816(acc1[1][1], axl[1], bh[2], bh[3]);
      mma16816(acc1[0][0], axh[0], bl[0], bl[1]);
      mma16816(acc1[0][1], axh[0], bl[2], bl[3]);
      mma16816(acc1[1][0], axh[1], bl[0], bl[1]);
      mma16816(acc1[1][1], axh[1], bl[2], bl[3]);
    }

    // ---- convert: bias + relu + split -> h images (own tile, no bar needed) ----
#pragma unroll
    for (int mt = 0; mt < 2; ++mt) {
      const int r0 = wr * 32 + mt * 16 + gid;
#pragma unroll
      for (int j = 0; j < 2; ++j) {
        const int cc = wc * 16 + j * 8 + 2 * tig;
        const float bb0 = bv[j * 2], bb1 = bv[j * 2 + 1];
        float v0 = fmaxf(acc1[mt][j][0] + bb0, 0.0f);
        float v1 = fmaxf(acc1[mt][j][1] + bb1, 0.0f);
        float v2 = fmaxf(acc1[mt][j][2] + bb0, 0.0f);
        float v3 = fmaxf(acc1[mt][j][3] + bb1, 0.0f);
        u32 h0, l0, h1, l1;
        split_pack(v0, v1, h0, l0);
        split_pack(v2, v3, h1, l1);
        u32 oa = swz(r0, cc), ob = swz(r0 + 8, cc);
        *(u32*)(smem_raw + SM_HHI + oa) = h0;
        *(u32*)(smem_raw + SM_HLO + oa) = l0;
        *(u32*)(smem_raw + SM_HHI + ob) = h1;
        *(u32*)(smem_raw + SM_HLO + ob) = l1;
      }
    }
    __syncthreads();          // h[kc] visible to all warps

    // ---- GEMM2(kc): warp tile 32 x 64, 192 MMAs ----
#pragma unroll
    for (int kt = 0; kt < 4; ++kt) {
      const int k0 = kt * 16;
      u32 ahh[2][4], ahl[2][4];
      ldsm4(a_addr(sm + SM_HHI, wr * 32,      k0, lr, lg), ahh[0]);
      ldsm4(a_addr(sm + SM_HHI, wr * 32 + 16, k0, lr, lg), ahh[1]);
      ldsm4(a_addr(sm + SM_HLO, wr * 32,      k0, lr, lg), ahl[0]);
      ldsm4(a_addr(sm + SM_HLO, wr * 32 + 16, k0, lr, lg), ahl[1]);
#pragma unroll
      for (int half = 0; half < 2; ++half) {
        u32 b2h[2][4], b2l[2][4];
#pragma unroll
        for (int t = 0; t < 2; ++t) {
          const int n0 = wc * 64 + (half * 2 + t) * 16;
          ldsm4(b_addr(sm + SM_W2,          n0, k0, lr, lg), b2h[t]);
          ldsm4(b_addr(sm + SM_W2 + 32768u, n0, k0, lr, lg), b2l[t]);
        }
        const int jb = half * 4;
#pragma unroll
        for (int t = 0; t < 2; ++t) {
          mma16816(acc2[0][jb + 2*t],     ahh[0], b2h[t][0], b2h[t][1]);
          mma16816(acc2[0][jb + 2*t + 1], ahh[0], b2h[t][2], b2h[t][3]);
          mma16816(acc2[1][jb + 2*t],     ahh[1], b2h[t][0], b2h[t][1]);
          mma16816(acc2[1][jb + 2*t + 1], ahh[1], b2h[t][2], b2h[t][3]);
        }
#pragma unroll
        for (int t = 0; t < 2; ++t) {
          mma16816(acc2[0][jb + 2*t],     ahl[0], b2h[t][0], b2h[t][1]);
          mma16816(acc2[0][jb + 2*t + 1], ahl[0], b2h[t][2], b2h[t][3]);
          mma16816(acc2[1][jb + 2*t],     ahl[1], b2h[t][0], b2h[t][1]);
          mma16816(acc2[1][jb + 2*t + 1], ahl[1], b2h[t][2], b2h[t][3]);
        }
#pragma unroll
        for (int t = 0; t < 2; ++t) {
          mma16816(acc2[0][jb + 2*t],     ahh[0], b2l[t][0], b2l[t][1]);
          mma16816(acc2[0][jb + 2*t + 1], ahh[0], b2l[t][2], b2l[t][3]);
          mma16816(acc2[1][jb + 2*t],     ahh[1], b2l[t][0], b2l[t][1]);
          mma16816(acc2[1][jb + 2*t + 1], ahh[1], b2l[t][2], b2l[t][3]);
        }
      }
    }
  }

  // ---- epilogue: + b2 (__ldg), store ----
#pragma unroll
  for (int mt = 0; mt < 2; ++mt) {
    const int r0 = row0 + wr * 32 + mt * 16 + gid;
#pragma unroll
    for (int j = 0; j < 8; ++j) {
      const int c = wc * 64 + j * 8 + 2 * tig;
      const float bb0 = __ldg(b2 + c), bb1 = __ldg(b2 + c + 1);
      float2 va = make_float2(acc2[mt][j][0] + bb0, acc2[mt][j][1] + bb1);
      float2 vb = make_float2(acc2[mt][j][2] + bb0, acc2[mt][j][3] + bb1);
      *(float2*)(out + (size_t)r0 * EDIM + c)       = va;
      *(float2*)(out + (size_t)(r0 + 8) * EDIM + c) = vb;
    }
  }
}

// ============================ launch ========================================
extern "C" void kernel_launch(void* const* d_in, const int* in_sizes, int n_in,
                              void* d_out, int out_size) {
  (void)in_sizes; (void)n_in; (void)out_size;
  const float* seq = (const float*)d_in[0];
  const float* W1  = (const float*)d_in[1];
  const float* b1  = (const float*)d_in[2];
  const float* W2  = (const float*)d_in[3];
  const float* b2  = (const float*)d_in[4];

  cudaFuncSetAttribute(seqfc_main, cudaFuncAttributeMaxDynamicSharedMemorySize,
                       SMEM_TOTAL);

  const int prep_total = NCHUNK * KC * K1PAD + NCHUNK * EDIM * K1PAD;
  prep_kernel<<<(prep_total + 255) / 256, 256>>>(W1, W2);
  seqfc_main<<<B_TOTAL / MTILE, NTHREADS, SMEM_TOTAL>>>(seq, b1, b2, (float*)d_out);
}

// round 8
// speedup vs baseline: 1.5523x; 1.4366x over previous
#include <cuda_runtime.h>
#include <cuda_fp16.h>
#include <stdint.h>

// ---------------------------------------------------------------------------
// SeqFCEncoder via warp-level mma.sync (compute_103 base ISA).
// R8: fp16 2-pass split GEMMs:  A*B ~= Ahi*Bhi + Alo*Bhi  (fp32 accum,
//     W rounded once to fp16; error ~2^-11 rel, well under 1e-3 gate).
//     -33% MMAs vs bf16 3-pass, halved weight images -> W1+W2 double-buffered
//     in 112KB, 2 CTAs/SM. Threefry dropout bit-exact (validated R1-R7).
// ---------------------------------------------------------------------------

typedef unsigned int u32;
typedef unsigned long long u64;

#define B_TOTAL   262144
#define LSEQ      50
#define HDIM      1024
#define EDIM      256
#define MTILE     64
#define NTHREADS  256
#define KC        64
#define NCHUNK    (HDIM / KC)     // 16
#define K1PAD     64

// ---- smem layout (bytes, dynamic) ----
#define SM_XHI   0               // 8KB  X hi fp16 [64 m][64 k] SW128
#define SM_XLO   8192            // 8KB  X lo
#define SM_HHI   16384           // 8KB  h hi (also fp32 x staging early)
#define SM_HLO   24576           // 8KB  h lo
#define SM_W1    32768           // 2 x 8KB double buffer (hi only)
#define W1BUFSZ  8192
#define SM_W2    49152           // 2 x 32KB double buffer (hi only)
#define W2BUFSZ  32768
#define SMEM_TOTAL 114688        // 112KB -> 2 CTAs/SM

// ---- pre-rounded fp16 weight images, SW128 K-major [n][k=64] ----
__device__ __align__(1024) unsigned char g_w1img[NCHUNK][KC   * K1PAD * 2]; // 128KB
__device__ __align__(1024) unsigned char g_w2img[NCHUNK][EDIM * K1PAD * 2]; // 512KB

// ============================ low-level helpers =============================
__device__ __forceinline__ u32 smem_u32_of(const void* p) {
  u32 a;
  asm("{ .reg .u64 t; cvta.to.shared.u64 t, %1; cvt.u32.u64 %0, t; }" : "=r"(a) : "l"(p));
  return a;
}
__device__ __forceinline__ u32 swz(int r, int k) {
  u32 off = ((u32)(r >> 3) << 10) | ((u32)(r & 7) << 7) | ((u32)k << 1);
  return off ^ ((off >> 3) & 0x70u);
}
__device__ __forceinline__ void ldsm4(u32 addr, u32 f[4]) {
  asm volatile("ldmatrix.sync.aligned.m8n8.x4.shared.b16 {%0,%1,%2,%3}, [%4];"
               : "=r"(f[0]), "=r"(f[1]), "=r"(f[2]), "=r"(f[3]) : "r"(addr));
}
__device__ __forceinline__ u32 a_addr(u32 img, int m0, int k0, int lr, int lg) {
  return img + swz(m0 + lr + ((lg & 1) << 3), k0 + ((lg >> 1) << 3));
}
__device__ __forceinline__ u32 b_addr(u32 img, int n0, int k0, int lr, int lg) {
  return img + swz(n0 + lr + ((lg >> 1) << 3), k0 + ((lg & 1) << 3));
}
__device__ __forceinline__ void mma16816(float c[4], const u32 a[4], u32 b0, u32 b1) {
  asm volatile(
    "mma.sync.aligned.m16n8k16.row.col.f32.f16.f16.f32 "
    "{%0,%1,%2,%3}, {%4,%5,%6,%7}, {%8,%9}, {%0,%1,%2,%3};"
    : "+f"(c[0]), "+f"(c[1]), "+f"(c[2]), "+f"(c[3])
    : "r"(a[0]), "r"(a[1]), "r"(a[2]), "r"(a[3]), "r"(b0), "r"(b1));
}
__device__ __forceinline__ void cpa16(u32 dst, const void* src) {
  asm volatile("cp.async.cg.shared.global [%0], [%1], 16;" :: "r"(dst), "l"(src));
}
#define CP_COMMIT() asm volatile("cp.async.commit_group;" ::: "memory")
#define CP_WAIT0()  asm volatile("cp.async.wait_group 0;" ::: "memory")

// ============================ threefry dropout ==============================
__device__ __forceinline__ u32 rotl32(u32 x, u32 r) { return __funnelshift_l(x, x, r); }
__device__ __forceinline__ void tf2x32(u32 x0, u32 x1, u32 &o0, u32 &o1) {
  const u32 ks0 = 0u, ks1 = 42u, ks2 = 0u ^ 42u ^ 0x1BD11BDAu;
  x0 += ks0; x1 += ks1;
#define TFR(r) { x0 += x1; x1 = rotl32(x1, r); x1 ^= x0; }
  TFR(13) TFR(15) TFR(26) TFR(6)
  x0 += ks1; x1 += ks2 + 1u;
  TFR(17) TFR(29) TFR(16) TFR(24)
  x0 += ks2; x1 += ks0 + 2u;
  TFR(13) TFR(15) TFR(26) TFR(6)
  x0 += ks0; x1 += ks1 + 3u;
  TFR(17) TFR(29) TFR(16) TFR(24)
  x0 += ks1; x1 += ks2 + 4u;
  TFR(13) TFR(15) TFR(26) TFR(6)
  x0 += ks2; x1 += ks0 + 5u;
#undef TFR
  o0 = x0; o1 = x1;
}
__device__ __forceinline__ bool drop_elem(u32 i) {   // validated rel_err 0.0 (R1)
  u32 o0, o1;
  tf2x32(0u, i, o0, o1);
  u32 bits = o0 ^ o1;
  float u = __uint_as_float((bits >> 9) | 0x3f800000u) - 1.0f;
  return u < 0.2f;
}

// ============================ fp16 split helpers ============================
__device__ __forceinline__ void split_pack(float a, float b, u32 &h, u32 &l) {
  __half ha = __float2half_rn(a);
  __half hb = __float2half_rn(b);
  __half la = __float2half_rn(a - __half2float(ha));
  __half lb = __float2half_rn(b - __half2float(hb));
  h = (u32)__half_as_ushort(ha) | ((u32)__half_as_ushort(hb) << 16);
  l = (u32)__half_as_ushort(la) | ((u32)__half_as_ushort(lb) << 16);
}

// ============================ prep kernel ===================================
// W1/W2 -> fp16 (round-to-nearest) SW128 images [n][k=64]; W1 zero-padded k>=50.
__global__ void prep_kernel(const float* __restrict__ W1,
                            const float* __restrict__ W2) {
  int idx = blockIdx.x * blockDim.x + threadIdx.x;
  const int N1 = NCHUNK * KC * K1PAD;        // 65536
  const int N2 = NCHUNK * EDIM * K1PAD;      // 262144
  if (idx < N1) {
    int kc = idx / (KC * K1PAD);
    int r  = idx - kc * (KC * K1PAD);
    int n = r / K1PAD, k = r - (r / K1PAD) * K1PAD;
    float w = (k < LSEQ) ? W1[(size_t)k * HDIM + kc * KC + n] : 0.0f;
    *(unsigned short*)&g_w1img[kc][swz(n, k)] =
        __half_as_ushort(__float2half_rn(w));
  } else if (idx < N1 + N2) {
    int r2 = idx - N1;
    int kc = r2 / (EDIM * K1PAD);
    int r  = r2 - kc * (EDIM * K1PAD);
    int n = r / K1PAD, k = r - (r / K1PAD) * K1PAD;
    float w = W2[(size_t)(kc * KC + k) * EDIM + n];
    *(unsigned short*)&g_w2img[kc][swz(n, k)] =
        __half_as_ushort(__float2half_rn(w));
  }
}

// ============================ main kernel ===================================
extern __shared__ __align__(1024) unsigned char smem_raw[];

__global__ void __launch_bounds__(NTHREADS, 2)
seqfc_main(const float* __restrict__ seq,
           const float* __restrict__ b1,
           const float* __restrict__ b2,
           float* __restrict__ out)
{
  const int tid  = threadIdx.x;
  const int wid  = tid >> 5;
  const int lane = tid & 31;
  const int lr   = lane & 7;
  const int lg   = lane >> 3;
  const int gid  = lane >> 2;
  const int tig  = lane & 3;
  const int wr   = wid >> 2;          // 2 row groups of 32 rows
  const int wc   = wid & 3;           // 4 col groups
  const int row0 = blockIdx.x * MTILE;

  const u32 sm = smem_u32_of(smem_raw);

  // ---- issue chunk-0 weight copies immediately (overlaps X stage) ----
  {
    const unsigned char* s1 = &g_w1img[0][0];
    for (int i = tid; i < 512; i += NTHREADS)
      cpa16(sm + SM_W1 + i * 16, s1 + (size_t)i * 16);
    const unsigned char* s2 = &g_w2img[0][0];
    for (int i = tid; i < 2048; i += NTHREADS)
      cpa16(sm + SM_W2 + i * 16, s2 + (size_t)i * 16);
    CP_COMMIT();
  }

  // ---- X stage (all 256 threads; 4 threads per row) ----
  {
    float* xs = (float*)(smem_raw + SM_HHI);       // fp32 staging, stride 52
    const float* sp = seq + (size_t)row0 * LSEQ;
    for (int idx = tid; idx < MTILE * LSEQ; idx += NTHREADS) {
      int r = idx / LSEQ, k = idx - r * LSEQ;
      xs[r * 52 + k] = sp[idx];
    }
    __syncthreads();

    const int xrow = tid >> 2;
    const int q    = tid & 3;
    float xv[16];
#pragma unroll
    for (int i = 0; i < 16; ++i) {
      int k = q * 16 + i;
      xv[i] = (k < LSEQ) ? xs[xrow * 52 + k] : 0.0f;
    }
    int f = LSEQ;
#pragma unroll
    for (int i = 15; i >= 0; --i) {
      int k = q * 16 + i;
      if (k < LSEQ && xv[i] == -1.0f) f = k;
    }
    f = min(f, __shfl_xor_sync(0xffffffffu, f, 1));
    f = min(f, __shfl_xor_sync(0xffffffffu, f, 2));
    const u32 gb = (u32)(row0 + xrow) * (u32)LSEQ;
#pragma unroll
    for (int i = 0; i < 16; ++i) {
      int k = q * 16 + i;
      if (k < f && drop_elem(gb + (u32)k)) xv[i] = 0.0f;
    }
#pragma unroll
    for (int c = 0; c < 8; ++c) {
      u32 h, l;
      split_pack(xv[2 * c], xv[2 * c + 1], h, l);
      u32 o = swz(xrow, q * 16 + 2 * c);
      *(u32*)(smem_raw + SM_XHI + o) = h;
      *(u32*)(smem_raw + SM_XLO + o) = l;
    }
  }

  // ---- GEMM2 accumulators: warp tile = 32 rows x 64 cols ----
  float acc2[2][8][4];
#pragma unroll
  for (int mt = 0; mt < 2; ++mt)
#pragma unroll
    for (int j = 0; j < 8; ++j)
#pragma unroll
      for (int q = 0; q < 4; ++q) acc2[mt][j][q] = 0.0f;

  // ---- chunk loop: W[kc] in buffer kc&1, prefetch W[kc+1] each iter ----
  for (int kc = 0; kc < NCHUNK; ++kc) {
    CP_WAIT0();
    __syncthreads();          // W[kc] ready; all GEMM2(kc-1) h-reads done; X ready

    if (kc + 1 < NCHUNK) {    // prefetch next chunk into other buffers
      const unsigned char* s1 = &g_w1img[kc + 1][0];
      u32 d1 = sm + SM_W1 + (u32)((kc + 1) & 1) * W1BUFSZ;
      for (int i = tid; i < 512; i += NTHREADS)
        cpa16(d1 + i * 16, s1 + (size_t)i * 16);
      const unsigned char* s2 = &g_w2img[kc + 1][0];
      u32 d2 = sm + SM_W2 + (u32)((kc + 1) & 1) * W2BUFSZ;
      for (int i = tid; i < 2048; i += NTHREADS)
        cpa16(d2 + i * 16, s2 + (size_t)i * 16);
      CP_COMMIT();
    }

    // bias prefetch for this chunk's convert
    float bv[4];
    {
      const int bb = kc * KC;
#pragma unroll
      for (int j = 0; j < 2; ++j) {
        int cc = bb + wc * 16 + j * 8 + 2 * tig;
        bv[j * 2]     = __ldg(b1 + cc);
        bv[j * 2 + 1] = __ldg(b1 + cc + 1);
      }
    }

    const u32 w1b = sm + SM_W1 + (u32)(kc & 1) * W1BUFSZ;
    const u32 w2b = sm + SM_W2 + (u32)(kc & 1) * W2BUFSZ;

    // ---- GEMM1(kc): 2-pass, warp tile 32 x 16, 32 MMAs ----
    float acc1[2][2][4];
#pragma unroll
    for (int mt = 0; mt < 2; ++mt)
#pragma unroll
      for (int j = 0; j < 2; ++j)
#pragma unroll
        for (int q = 0; q < 4; ++q) acc1[mt][j][q] = 0.0f;

#pragma unroll
    for (int kt = 0; kt < 4; ++kt) {
      const int k0 = kt * 16;
      u32 axh[2][4], axl[2][4];
      ldsm4(a_addr(sm + SM_XHI, wr * 32,      k0, lr, lg), axh[0]);
      ldsm4(a_addr(sm + SM_XHI, wr * 32 + 16, k0, lr, lg), axh[1]);
      ldsm4(a_addr(sm + SM_XLO, wr * 32,      k0, lr, lg), axl[0]);
      ldsm4(a_addr(sm + SM_XLO, wr * 32 + 16, k0, lr, lg), axl[1]);
      u32 bh[4];
      ldsm4(b_addr(w1b, wc * 16, k0, lr, lg), bh);
      mma16816(acc1[0][0], axh[0], bh[0], bh[1]);
      mma16816(acc1[0][1], axh[0], bh[2], bh[3]);
      mma16816(acc1[1][0], axh[1], bh[0], bh[1]);
      mma16816(acc1[1][1], axh[1], bh[2], bh[3]);
      mma16816(acc1[0][0], axl[0], bh[0], bh[1]);
      mma16816(acc1[0][1], axl[0], bh[2], bh[3]);
      mma16816(acc1[1][0], axl[1], bh[0], bh[1]);
      mma16816(acc1[1][1], axl[1], bh[2], bh[3]);
    }

    // ---- convert: bias + relu + fp16 split -> h images ----
#pragma unroll
    for (int mt = 0; mt < 2; ++mt) {
      const int r0 = wr * 32 + mt * 16 + gid;
#pragma unroll
      for (int j = 0; j < 2; ++j) {
        const int cc = wc * 16 + j * 8 + 2 * tig;
        const float bb0 = bv[j * 2], bb1 = bv[j * 2 + 1];
        float v0 = fmaxf(acc1[mt][j][0] + bb0, 0.0f);
        float v1 = fmaxf(acc1[mt][j][1] + bb1, 0.0f);
        float v2 = fmaxf(acc1[mt][j][2] + bb0, 0.0f);
        float v3 = fmaxf(acc1[mt][j][3] + bb1, 0.0f);
        u32 h0, l0, h1, l1;
        split_pack(v0, v1, h0, l0);
        split_pack(v2, v3, h1, l1);
        u32 oa = swz(r0, cc), ob = swz(r0 + 8, cc);
        *(u32*)(smem_raw + SM_HHI + oa) = h0;
        *(u32*)(smem_raw + SM_HLO + oa) = l0;
        *(u32*)(smem_raw + SM_HHI + ob) = h1;
        *(u32*)(smem_raw + SM_HLO + ob) = l1;
      }
    }
    __syncthreads();          // h[kc] visible to all warps

    // ---- GEMM2(kc): 2-pass, warp tile 32 x 64, 128 MMAs ----
#pragma unroll
    for (int kt = 0; kt < 4; ++kt) {
      const int k0 = kt * 16;
      u32 ahh[2][4], ahl[2][4];
      ldsm4(a_addr(sm + SM_HHI, wr * 32,      k0, lr, lg), ahh[0]);
      ldsm4(a_addr(sm + SM_HHI, wr * 32 + 16, k0, lr, lg), ahh[1]);
      ldsm4(a_addr(sm + SM_HLO, wr * 32,      k0, lr, lg), ahl[0]);
      ldsm4(a_addr(sm + SM_HLO, wr * 32 + 16, k0, lr, lg), ahl[1]);
      u32 bf[4][4];
#pragma unroll
      for (int t = 0; t < 4; ++t)
        ldsm4(b_addr(w2b, wc * 64 + t * 16, k0, lr, lg), bf[t]);
      // hi pass (16 distinct accumulators before any reuse)
#pragma unroll
      for (int t = 0; t < 4; ++t) {
        mma16816(acc2[0][2*t],     ahh[0], bf[t][0], bf[t][1]);
        mma16816(acc2[0][2*t + 1], ahh[0], bf[t][2], bf[t][3]);
        mma16816(acc2[1][2*t],     ahh[1], bf[t][0], bf[t][1]);
        mma16816(acc2[1][2*t + 1], ahh[1], bf[t][2], bf[t][3]);
      }
      // lo pass
#pragma unroll
      for (int t = 0; t < 4; ++t) {
        mma16816(acc2[0][2*t],     ahl[0], bf[t][0], bf[t][1]);
        mma16816(acc2[0][2*t + 1], ahl[0], bf[t][2], bf[t][3]);
        mma16816(acc2[1][2*t],     ahl[1], bf[t][0], bf[t][1]);
        mma16816(acc2[1][2*t + 1], ahl[1], bf[t][2], bf[t][3]);
      }
    }
  }

  // ---- epilogue: + b2 (__ldg), store ----
#pragma unroll
  for (int mt = 0; mt < 2; ++mt) {
    const int r0 = row0 + wr * 32 + mt * 16 + gid;
#pragma unroll
    for (int j = 0; j < 8; ++j) {
      const int c = wc * 64 + j * 8 + 2 * tig;
      const float bb0 = __ldg(b2 + c), bb1 = __ldg(b2 + c + 1);
      float2 va = make_float2(acc2[mt][j][0] + bb0, acc2[mt][j][1] + bb1);
      float2 vb = make_float2(acc2[mt][j][2] + bb0, acc2[mt][j][3] + bb1);
      *(float2*)(out + (size_t)r0 * EDIM + c)       = va;
      *(float2*)(out + (size_t)(r0 + 8) * EDIM + c) = vb;
    }
  }
}

// ============================ launch ========================================
extern "C" void kernel_launch(void* const* d_in, const int* in_sizes, int n_in,
                              void* d_out, int out_size) {
  (void)in_sizes; (void)n_in; (void)out_size;
  const float* seq = (const float*)d_in[0];
  const float* W1  = (const float*)d_in[1];
  const float* b1  = (const float*)d_in[2];
  const float* W2  = (const float*)d_in[3];
  const float* b2  = (const float*)d_in[4];

  cudaFuncSetAttribute(seqfc_main, cudaFuncAttributeMaxDynamicSharedMemorySize,
                       SMEM_TOTAL);

  const int prep_total = NCHUNK * KC * K1PAD + NCHUNK * EDIM * K1PAD;
  prep_kernel<<<(prep_total + 255) / 256, 256>>>(W1, W2);
  seqfc_main<<<B_TOTAL / MTILE, NTHREADS, SMEM_TOTAL>>>(seq, b1, b2, (float*)d_out);
}

// round 9
// speedup vs baseline: 2.1179x; 1.3643x over previous
#include <cuda_runtime.h>
#include <cuda_fp16.h>
#include <stdint.h>

// ---------------------------------------------------------------------------
// SeqFCEncoder via warp-level mma.sync (compute_103 base ISA).
// R9: GEMM1 fp16 2-pass (x split hi+lo), GEMM2 fp16 1-pass (h rounded once).
//     96 MMAs/warp/chunk vs R8's 160. Expected rel_err ~4.3e-4 (< 1e-3 gate).
//     2 CTAs/SM, W1+W2 double-buffered. Threefry dropout bit-exact.
// ---------------------------------------------------------------------------

typedef unsigned int u32;
typedef unsigned long long u64;

#define B_TOTAL   262144
#define LSEQ      50
#define HDIM      1024
#define EDIM      256
#define MTILE     64
#define NTHREADS  256
#define KC        64
#define NCHUNK    (HDIM / KC)     // 16
#define K1PAD     64

// ---- smem layout (bytes, dynamic) ----
#define SM_XHI   0               // 8KB  X hi fp16 [64 m][64 k] SW128
#define SM_XLO   8192            // 8KB  X lo
#define SM_H     16384           // 8KB  h fp16 (also fp32 x staging early.. no: staging needs 13KB)
#define SM_STAGE 16384           // staging overlaps SM_H + beyond (pre-loop only)
#define SM_W1    32768           // 2 x 8KB double buffer
#define W1BUFSZ  8192
#define SM_W2    49152           // 2 x 32KB double buffer
#define W2BUFSZ  32768
#define SMEM_TOTAL 114688        // 112KB -> 2 CTAs/SM

// ---- pre-rounded fp16 weight images, SW128 K-major [n][k=64] ----
__device__ __align__(1024) unsigned char g_w1img[NCHUNK][KC   * K1PAD * 2]; // 128KB
__device__ __align__(1024) unsigned char g_w2img[NCHUNK][EDIM * K1PAD * 2]; // 512KB

// ============================ low-level helpers =============================
__device__ __forceinline__ u32 smem_u32_of(const void* p) {
  u32 a;
  asm("{ .reg .u64 t; cvta.to.shared.u64 t, %1; cvt.u32.u64 %0, t; }" : "=r"(a) : "l"(p));
  return a;
}
__device__ __forceinline__ u32 swz(int r, int k) {
  u32 off = ((u32)(r >> 3) << 10) | ((u32)(r & 7) << 7) | ((u32)k << 1);
  return off ^ ((off >> 3) & 0x70u);
}
__device__ __forceinline__ void ldsm4(u32 addr, u32 f[4]) {
  asm volatile("ldmatrix.sync.aligned.m8n8.x4.shared.b16 {%0,%1,%2,%3}, [%4];"
               : "=r"(f[0]), "=r"(f[1]), "=r"(f[2]), "=r"(f[3]) : "r"(addr));
}
__device__ __forceinline__ u32 a_addr(u32 img, int m0, int k0, int lr, int lg) {
  return img + swz(m0 + lr + ((lg & 1) << 3), k0 + ((lg >> 1) << 3));
}
__device__ __forceinline__ u32 b_addr(u32 img, int n0, int k0, int lr, int lg) {
  return img + swz(n0 + lr + ((lg >> 1) << 3), k0 + ((lg & 1) << 3));
}
__device__ __forceinline__ void mma16816(float c[4], const u32 a[4], u32 b0, u32 b1) {
  asm volatile(
    "mma.sync.aligned.m16n8k16.row.col.f32.f16.f16.f32 "
    "{%0,%1,%2,%3}, {%4,%5,%6,%7}, {%8,%9}, {%0,%1,%2,%3};"
    : "+f"(c[0]), "+f"(c[1]), "+f"(c[2]), "+f"(c[3])
    : "r"(a[0]), "r"(a[1]), "r"(a[2]), "r"(a[3]), "r"(b0), "r"(b1));
}
__device__ __forceinline__ void cpa16(u32 dst, const void* src) {
  asm volatile("cp.async.cg.shared.global [%0], [%1], 16;" :: "r"(dst), "l"(src));
}
#define CP_COMMIT() asm volatile("cp.async.commit_group;" ::: "memory")
#define CP_WAIT0()  asm volatile("cp.async.wait_group 0;" ::: "memory")

// ============================ threefry dropout ==============================
__device__ __forceinline__ u32 rotl32(u32 x, u32 r) { return __funnelshift_l(x, x, r); }
__device__ __forceinline__ void tf2x32(u32 x0, u32 x1, u32 &o0, u32 &o1) {
  const u32 ks0 = 0u, ks1 = 42u, ks2 = 0u ^ 42u ^ 0x1BD11BDAu;
  x0 += ks0; x1 += ks1;
#define TFR(r) { x0 += x1; x1 = rotl32(x1, r); x1 ^= x0; }
  TFR(13) TFR(15) TFR(26) TFR(6)
  x0 += ks1; x1 += ks2 + 1u;
  TFR(17) TFR(29) TFR(16) TFR(24)
  x0 += ks2; x1 += ks0 + 2u;
  TFR(13) TFR(15) TFR(26) TFR(6)
  x0 += ks0; x1 += ks1 + 3u;
  TFR(17) TFR(29) TFR(16) TFR(24)
  x0 += ks1; x1 += ks2 + 4u;
  TFR(13) TFR(15) TFR(26) TFR(6)
  x0 += ks2; x1 += ks0 + 5u;
#undef TFR
  o0 = x0; o1 = x1;
}
__device__ __forceinline__ bool drop_elem(u32 i) {   // validated rel_err 0.0 (R1)
  u32 o0, o1;
  tf2x32(0u, i, o0, o1);
  u32 bits = o0 ^ o1;
  float u = __uint_as_float((bits >> 9) | 0x3f800000u) - 1.0f;
  return u < 0.2f;
}

// ============================ fp16 pack helpers =============================
__device__ __forceinline__ void split_pack(float a, float b, u32 &h, u32 &l) {
  __half ha = __float2half_rn(a);
  __half hb = __float2half_rn(b);
  __half la = __float2half_rn(a - __half2float(ha));
  __half lb = __float2half_rn(b - __half2float(hb));
  h = (u32)__half_as_ushort(ha) | ((u32)__half_as_ushort(hb) << 16);
  l = (u32)__half_as_ushort(la) | ((u32)__half_as_ushort(lb) << 16);
}
__device__ __forceinline__ u32 pack_h2(float a, float b) {
  return (u32)__half_as_ushort(__float2half_rn(a))
       | ((u32)__half_as_ushort(__float2half_rn(b)) << 16);
}

// ============================ prep kernel ===================================
__global__ void prep_kernel(const float* __restrict__ W1,
                            const float* __restrict__ W2) {
  int idx = blockIdx.x * blockDim.x + threadIdx.x;
  const int N1 = NCHUNK * KC * K1PAD;        // 65536
  const int N2 = NCHUNK * EDIM * K1PAD;      // 262144
  if (idx < N1) {
    int kc = idx / (KC * K1PAD);
    int r  = idx - kc * (KC * K1PAD);
    int n = r / K1PAD, k = r - (r / K1PAD) * K1PAD;
    float w = (k < LSEQ) ? W1[(size_t)k * HDIM + kc * KC + n] : 0.0f;
    *(unsigned short*)&g_w1img[kc][swz(n, k)] =
        __half_as_ushort(__float2half_rn(w));
  } else if (idx < N1 + N2) {
    int r2 = idx - N1;
    int kc = r2 / (EDIM * K1PAD);
    int r  = r2 - kc * (EDIM * K1PAD);
    int n = r / K1PAD, k = r - (r / K1PAD) * K1PAD;
    float w = W2[(size_t)(kc * KC + k) * EDIM + n];
    *(unsigned short*)&g_w2img[kc][swz(n, k)] =
        __half_as_ushort(__float2half_rn(w));
  }
}

// ============================ main kernel ===================================
extern __shared__ __align__(1024) unsigned char smem_raw[];

__global__ void __launch_bounds__(NTHREADS, 2)
seqfc_main(const float* __restrict__ seq,
           const float* __restrict__ b1,
           const float* __restrict__ b2,
           float* __restrict__ out)
{
  const int tid  = threadIdx.x;
  const int wid  = tid >> 5;
  const int lane = tid & 31;
  const int lr   = lane & 7;
  const int lg   = lane >> 3;
  const int gid  = lane >> 2;
  const int tig  = lane & 3;
  const int wr   = wid >> 2;          // 2 row groups of 32 rows
  const int wc   = wid & 3;           // 4 col groups
  const int row0 = blockIdx.x * MTILE;

  const u32 sm = smem_u32_of(smem_raw);

  // ---- issue chunk-0 weight copies immediately (overlaps X stage) ----
  {
    const unsigned char* s1 = &g_w1img[0][0];
    for (int i = tid; i < 512; i += NTHREADS)
      cpa16(sm + SM_W1 + i * 16, s1 + (size_t)i * 16);
    const unsigned char* s2 = &g_w2img[0][0];
    for (int i = tid; i < 2048; i += NTHREADS)
      cpa16(sm + SM_W2 + i * 16, s2 + (size_t)i * 16);
    CP_COMMIT();
  }

  // ---- X stage (all 256 threads; 4 threads per row) ----
  {
    float* xs = (float*)(smem_raw + SM_STAGE);     // fp32 staging, stride 52
    const float* sp = seq + (size_t)row0 * LSEQ;
    for (int idx = tid; idx < MTILE * LSEQ; idx += NTHREADS) {
      int r = idx / LSEQ, k = idx - r * LSEQ;
      xs[r * 52 + k] = sp[idx];
    }
    __syncthreads();

    const int xrow = tid >> 2;
    const int q    = tid & 3;
    float xv[16];
#pragma unroll
    for (int i = 0; i < 16; ++i) {
      int k = q * 16 + i;
      xv[i] = (k < LSEQ) ? xs[xrow * 52 + k] : 0.0f;
    }
    int f = LSEQ;
#pragma unroll
    for (int i = 15; i >= 0; --i) {
      int k = q * 16 + i;
      if (k < LSEQ && xv[i] == -1.0f) f = k;
    }
    f = min(f, __shfl_xor_sync(0xffffffffu, f, 1));
    f = min(f, __shfl_xor_sync(0xffffffffu, f, 2));
    const u32 gb = (u32)(row0 + xrow) * (u32)LSEQ;
#pragma unroll
    for (int i = 0; i < 16; ++i) {
      int k = q * 16 + i;
      if (k < f && drop_elem(gb + (u32)k)) xv[i] = 0.0f;
    }
    __syncthreads();          // staging reads done before X image writes? X imgs disjoint; this bar guards SM_STAGE reuse as h
#pragma unroll
    for (int c = 0; c < 8; ++c) {
      u32 h, l;
      split_pack(xv[2 * c], xv[2 * c + 1], h, l);
      u32 o = swz(xrow, q * 16 + 2 * c);
      *(u32*)(smem_raw + SM_XHI + o) = h;
      *(u32*)(smem_raw + SM_XLO + o) = l;
    }
  }

  // ---- GEMM2 accumulators: warp tile = 32 rows x 64 cols ----
  float acc2[2][8][4];
#pragma unroll
  for (int mt = 0; mt < 2; ++mt)
#pragma unroll
    for (int j = 0; j < 8; ++j)
#pragma unroll
      for (int q = 0; q < 4; ++q) acc2[mt][j][q] = 0.0f;

  // ---- chunk loop: W[kc] in buffer kc&1, prefetch W[kc+1] each iter ----
  for (int kc = 0; kc < NCHUNK; ++kc) {
    CP_WAIT0();
    __syncthreads();          // W[kc] ready; GEMM2(kc-1) h-reads done; X ready

    if (kc + 1 < NCHUNK) {    // prefetch next chunk into other buffers
      const unsigned char* s1 = &g_w1img[kc + 1][0];
      u32 d1 = sm + SM_W1 + (u32)((kc + 1) & 1) * W1BUFSZ;
      for (int i = tid; i < 512; i += NTHREADS)
        cpa16(d1 + i * 16, s1 + (size_t)i * 16);
      const unsigned char* s2 = &g_w2img[kc + 1][0];
      u32 d2 = sm + SM_W2 + (u32)((kc + 1) & 1) * W2BUFSZ;
      for (int i = tid; i < 2048; i += NTHREADS)
        cpa16(d2 + i * 16, s2 + (size_t)i * 16);
      CP_COMMIT();
    }

    // bias prefetch for this chunk's convert
    float bv[4];
    {
      const int bb = kc * KC;
#pragma unroll
      for (int j = 0; j < 2; ++j) {
        int cc = bb + wc * 16 + j * 8 + 2 * tig;
        bv[j * 2]     = __ldg(b1 + cc);
        bv[j * 2 + 1] = __ldg(b1 + cc + 1);
      }
    }

    const u32 w1b = sm + SM_W1 + (u32)(kc & 1) * W1BUFSZ;
    const u32 w2b = sm + SM_W2 + (u32)(kc & 1) * W2BUFSZ;

    // ---- GEMM1(kc): 2-pass, warp tile 32 x 16, 32 MMAs ----
    float acc1[2][2][4];
#pragma unroll
    for (int mt = 0; mt < 2; ++mt)
#pragma unroll
      for (int j = 0; j < 2; ++j)
#pragma unroll
        for (int q = 0; q < 4; ++q) acc1[mt][j][q] = 0.0f;

#pragma unroll
    for (int kt = 0; kt < 4; ++kt) {
      const int k0 = kt * 16;
      u32 axh[2][4], axl[2][4];
      ldsm4(a_addr(sm + SM_XHI, wr * 32,      k0, lr, lg), axh[0]);
      ldsm4(a_addr(sm + SM_XHI, wr * 32 + 16, k0, lr, lg), axh[1]);
      ldsm4(a_addr(sm + SM_XLO, wr * 32,      k0, lr, lg), axl[0]);
      ldsm4(a_addr(sm + SM_XLO, wr * 32 + 16, k0, lr, lg), axl[1]);
      u32 bh[4];
      ldsm4(b_addr(w1b, wc * 16, k0, lr, lg), bh);
      mma16816(acc1[0][0], axh[0], bh[0], bh[1]);
      mma16816(acc1[0][1], axh[0], bh[2], bh[3]);
      mma16816(acc1[1][0], axh[1], bh[0], bh[1]);
      mma16816(acc1[1][1], axh[1], bh[2], bh[3]);
      mma16816(acc1[0][0], axl[0], bh[0], bh[1]);
      mma16816(acc1[0][1], axl[0], bh[2], bh[3]);
      mma16816(acc1[1][0], axl[1], bh[0], bh[1]);
      mma16816(acc1[1][1], axl[1], bh[2], bh[3]);
    }

    // ---- convert: bias + relu -> single fp16 h image ----
#pragma unroll
    for (int mt = 0; mt < 2; ++mt) {
      const int r0 = wr * 32 + mt * 16 + gid;
#pragma unroll
      for (int j = 0; j < 2; ++j) {
        const int cc = wc * 16 + j * 8 + 2 * tig;
        const float bb0 = bv[j * 2], bb1 = bv[j * 2 + 1];
        float v0 = fmaxf(acc1[mt][j][0] + bb0, 0.0f);
        float v1 = fmaxf(acc1[mt][j][1] + bb1, 0.0f);
        float v2 = fmaxf(acc1[mt][j][2] + bb0, 0.0f);
        float v3 = fmaxf(acc1[mt][j][3] + bb1, 0.0f);
        *(u32*)(smem_raw + SM_H + swz(r0, cc))     = pack_h2(v0, v1);
        *(u32*)(smem_raw + SM_H + swz(r0 + 8, cc)) = pack_h2(v2, v3);
      }
    }
    __syncthreads();          // h[kc] visible to all warps

    // ---- GEMM2(kc): 1-pass, warp tile 32 x 64, 64 MMAs ----
#pragma unroll
    for (int kt = 0; kt < 4; ++kt) {
      const int k0 = kt * 16;
      u32 ah[2][4];
      ldsm4(a_addr(sm + SM_H, wr * 32,      k0, lr, lg), ah[0]);
      ldsm4(a_addr(sm + SM_H, wr * 32 + 16, k0, lr, lg), ah[1]);
      u32 bf[4][4];
#pragma unroll
      for (int t = 0; t < 4; ++t)
        ldsm4(b_addr(w2b, wc * 64 + t * 16, k0, lr, lg), bf[t]);
#pragma unroll
      for (int t = 0; t < 4; ++t) {
        mma16816(acc2[0][2*t],     ah[0], bf[t][0], bf[t][1]);
        mma16816(acc2[0][2*t + 1], ah[0], bf[t][2], bf[t][3]);
        mma16816(acc2[1][2*t],     ah[1], bf[t][0], bf[t][1]);
        mma16816(acc2[1][2*t + 1], ah[1], bf[t][2], bf[t][3]);
      }
    }
  }

  // ---- epilogue: + b2 (__ldg), store ----
#pragma unroll
  for (int mt = 0; mt < 2; ++mt) {
    const int r0 = row0 + wr * 32 + mt * 16 + gid;
#pragma unroll
    for (int j = 0; j < 8; ++j) {
      const int c = wc * 64 + j * 8 + 2 * tig;
      const float bb0 = __ldg(b2 + c), bb1 = __ldg(b2 + c + 1);
      float2 va = make_float2(acc2[mt][j][0] + bb0, acc2[mt][j][1] + bb1);
      float2 vb = make_float2(acc2[mt][j][2] + bb0, acc2[mt][j][3] + bb1);
      *(float2*)(out + (size_t)r0 * EDIM + c)       = va;
      *(float2*)(out + (size_t)(r0 + 8) * EDIM + c) = vb;
    }
  }
}

// ============================ launch ========================================
extern "C" void kernel_launch(void* const* d_in, const int* in_sizes, int n_in,
                              void* d_out, int out_size) {
  (void)in_sizes; (void)n_in; (void)out_size;
  const float* seq = (const float*)d_in[0];
  const float* W1  = (const float*)d_in[1];
  const float* b1  = (const float*)d_in[2];
  const float* W2  = (const float*)d_in[3];
  const float* b2  = (const float*)d_in[4];

  cudaFuncSetAttribute(seqfc_main, cudaFuncAttributeMaxDynamicSharedMemorySize,
                       SMEM_TOTAL);

  const int prep_total = NCHUNK * KC * K1PAD + NCHUNK * EDIM * K1PAD;
  prep_kernel<<<(prep_total + 255) / 256, 256>>>(W1, W2);
  seqfc_main<<<B_TOTAL / MTILE, NTHREADS, SMEM_TOTAL>>>(seq, b1, b2, (float*)d_out);
}

// round 10
// speedup vs baseline: 2.1366x; 1.0089x over previous
#include <cuda_runtime.h>
#include <cuda_fp16.h>
#include <stdint.h>

// ---------------------------------------------------------------------------
// SeqFCEncoder via warp-level mma.sync (compute_103 base ISA).
// R10: both GEMMs 1-pass fp16 (x, W1, W2, h each rounded once; fp32 accum).
//      MTILE=32, warp tile 32x32, ~80 regs -> 3 CTAs/SM (24 warps).
//      Threefry dropout bit-exact (validated R1-R9).
// ---------------------------------------------------------------------------

typedef unsigned int u32;
typedef unsigned long long u64;

#define B_TOTAL   262144
#define LSEQ      50
#define HDIM      1024
#define EDIM      256
#define MTILE     32
#define NTHREADS  256
#define KC        64
#define NCHUNK    (HDIM / KC)     // 16
#define K1PAD     64

// ---- smem layout (bytes, dynamic) ----
#define SM_X     0               // 4KB  X fp16 [32 m][64 k] SW128
#define SM_H     4096            // 4KB  h fp16 [32 m][64 k] SW128
#define SM_W1    8192            // 2 x 8KB double buffer
#define W1BUFSZ  8192
#define SM_W2    24576           // 32KB single buffer (staging overlay pre-loop)
#define SMEM_TOTAL 57344         // 56KB -> 3 CTAs/SM (168KB)

// ---- pre-rounded fp16 weight images, SW128 K-major [n][k=64] ----
__device__ __align__(1024) unsigned char g_w1img[NCHUNK][KC   * K1PAD * 2]; // 128KB
__device__ __align__(1024) unsigned char g_w2img[NCHUNK][EDIM * K1PAD * 2]; // 512KB

// ============================ low-level helpers =============================
__device__ __forceinline__ u32 smem_u32_of(const void* p) {
  u32 a;
  asm("{ .reg .u64 t; cvta.to.shared.u64 t, %1; cvt.u32.u64 %0, t; }" : "=r"(a) : "l"(p));
  return a;
}
__device__ __forceinline__ u32 swz(int r, int k) {
  u32 off = ((u32)(r >> 3) << 10) | ((u32)(r & 7) << 7) | ((u32)k << 1);
  return off ^ ((off >> 3) & 0x70u);
}
__device__ __forceinline__ void ldsm4(u32 addr, u32 f[4]) {
  asm volatile("ldmatrix.sync.aligned.m8n8.x4.shared.b16 {%0,%1,%2,%3}, [%4];"
               : "=r"(f[0]), "=r"(f[1]), "=r"(f[2]), "=r"(f[3]) : "r"(addr));
}
__device__ __forceinline__ u32 a_addr(u32 img, int m0, int k0, int lr, int lg) {
  return img + swz(m0 + lr + ((lg & 1) << 3), k0 + ((lg >> 1) << 3));
}
__device__ __forceinline__ u32 b_addr(u32 img, int n0, int k0, int lr, int lg) {
  return img + swz(n0 + lr + ((lg >> 1) << 3), k0 + ((lg & 1) << 3));
}
__device__ __forceinline__ void mma16816(float c[4], const u32 a[4], u32 b0, u32 b1) {
  asm volatile(
    "mma.sync.aligned.m16n8k16.row.col.f32.f16.f16.f32 "
    "{%0,%1,%2,%3}, {%4,%5,%6,%7}, {%8,%9}, {%0,%1,%2,%3};"
    : "+f"(c[0]), "+f"(c[1]), "+f"(c[2]), "+f"(c[3])
    : "r"(a[0]), "r"(a[1]), "r"(a[2]), "r"(a[3]), "r"(b0), "r"(b1));
}
__device__ __forceinline__ void cpa16(u32 dst, const void* src) {
  asm volatile("cp.async.cg.shared.global [%0], [%1], 16;" :: "r"(dst), "l"(src));
}
#define CP_COMMIT() asm volatile("cp.async.commit_group;" ::: "memory")
#define CP_WAIT0()  asm volatile("cp.async.wait_group 0;" ::: "memory")

// ============================ threefry dropout ==============================
__device__ __forceinline__ u32 rotl32(u32 x, u32 r) { return __funnelshift_l(x, x, r); }
__device__ __forceinline__ void tf2x32(u32 x0, u32 x1, u32 &o0, u32 &o1) {
  const u32 ks0 = 0u, ks1 = 42u, ks2 = 0u ^ 42u ^ 0x1BD11BDAu;
  x0 += ks0; x1 += ks1;
#define TFR(r) { x0 += x1; x1 = rotl32(x1, r); x1 ^= x0; }
  TFR(13) TFR(15) TFR(26) TFR(6)
  x0 += ks1; x1 += ks2 + 1u;
  TFR(17) TFR(29) TFR(16) TFR(24)
  x0 += ks2; x1 += ks0 + 2u;
  TFR(13) TFR(15) TFR(26) TFR(6)
  x0 += ks0; x1 += ks1 + 3u;
  TFR(17) TFR(29) TFR(16) TFR(24)
  x0 += ks1; x1 += ks2 + 4u;
  TFR(13) TFR(15) TFR(26) TFR(6)
  x0 += ks2; x1 += ks0 + 5u;
#undef TFR
  o0 = x0; o1 = x1;
}
__device__ __forceinline__ bool drop_elem(u32 i) {   // validated rel_err 0.0 (R1)
  u32 o0, o1;
  tf2x32(0u, i, o0, o1);
  u32 bits = o0 ^ o1;
  float u = __uint_as_float((bits >> 9) | 0x3f800000u) - 1.0f;
  return u < 0.2f;
}

__device__ __forceinline__ u32 pack_h2(float a, float b) {
  return (u32)__half_as_ushort(__float2half_rn(a))
       | ((u32)__half_as_ushort(__float2half_rn(b)) << 16);
}

// ============================ prep kernel ===================================
__global__ void prep_kernel(const float* __restrict__ W1,
                            const float* __restrict__ W2) {
  int idx = blockIdx.x * blockDim.x + threadIdx.x;
  const int N1 = NCHUNK * KC * K1PAD;        // 65536
  const int N2 = NCHUNK * EDIM * K1PAD;      // 262144
  if (idx < N1) {
    int kc = idx / (KC * K1PAD);
    int r  = idx - kc * (KC * K1PAD);
    int n = r / K1PAD, k = r - (r / K1PAD) * K1PAD;
    float w = (k < LSEQ) ? W1[(size_t)k * HDIM + kc * KC + n] : 0.0f;
    *(unsigned short*)&g_w1img[kc][swz(n, k)] =
        __half_as_ushort(__float2half_rn(w));
  } else if (idx < N1 + N2) {
    int r2 = idx - N1;
    int kc = r2 / (EDIM * K1PAD);
    int r  = r2 - kc * (EDIM * K1PAD);
    int n = r / K1PAD, k = r - (r / K1PAD) * K1PAD;
    float w = W2[(size_t)(kc * KC + k) * EDIM + n];
    *(unsigned short*)&g_w2img[kc][swz(n, k)] =
        __half_as_ushort(__float2half_rn(w));
  }
}

// ============================ main kernel ===================================
extern __shared__ __align__(1024) unsigned char smem_raw[];

__global__ void __launch_bounds__(NTHREADS, 3)
seqfc_main(const float* __restrict__ seq,
           const float* __restrict__ b1,
           const float* __restrict__ b2,
           float* __restrict__ out)
{
  const int tid  = threadIdx.x;
  const int wid  = tid >> 5;
  const int lane = tid & 31;
  const int lr   = lane & 7;
  const int lg   = lane >> 3;
  const int gid  = lane >> 2;
  const int tig  = lane & 3;
  const int wr1  = wid >> 2;          // GEMM1: 2 row groups of 16
  const int wc1  = wid & 3;           // GEMM1: 4 col groups of 16
  const int row0 = blockIdx.x * MTILE;

  const u32 sm = smem_u32_of(smem_raw);

  // ---- prologue: W1[0] copy (overlaps X stage) ----
  {
    const unsigned char* s1 = &g_w1img[0][0];
    for (int i = tid; i < 512; i += NTHREADS)
      cpa16(sm + SM_W1 + i * 16, s1 + (size_t)i * 16);
    CP_COMMIT();
  }

  // ---- X stage: staging overlays SM_W2 (free until first W2 copy) ----
  {
    float* xs = (float*)(smem_raw + SM_W2);        // fp32 staging, stride 52
    const float* sp = seq + (size_t)row0 * LSEQ;
    for (int idx = tid; idx < MTILE * LSEQ; idx += NTHREADS) {
      int r = idx / LSEQ, k = idx - r * LSEQ;
      xs[r * 52 + k] = sp[idx];
    }
    __syncthreads();

    if (tid < MTILE * 4) {
      const int xrow = tid >> 2;
      const int q    = tid & 3;
      float xv[16];
#pragma unroll
      for (int i = 0; i < 16; ++i) {
        int k = q * 16 + i;
        xv[i] = (k < LSEQ) ? xs[xrow * 52 + k] : 0.0f;
      }
      int f = LSEQ;
#pragma unroll
      for (int i = 15; i >= 0; --i) {
        int k = q * 16 + i;
        if (k < LSEQ && xv[i] == -1.0f) f = k;
      }
      f = min(f, __shfl_xor_sync(0xffffffffu, f, 1));
      f = min(f, __shfl_xor_sync(0xffffffffu, f, 2));
      const u32 gb = (u32)(row0 + xrow) * (u32)LSEQ;
#pragma unroll
      for (int i = 0; i < 16; ++i) {
        int k = q * 16 + i;
        if (k < f && drop_elem(gb + (u32)k)) xv[i] = 0.0f;
      }
#pragma unroll
      for (int c = 0; c < 8; ++c) {
        u32 o = swz(xrow, q * 16 + 2 * c);
        *(u32*)(smem_raw + SM_X + o) = pack_h2(xv[2 * c], xv[2 * c + 1]);
      }
    }
  }

  CP_WAIT0();
  __syncthreads();            // X image + W1[0] ready; staging reads done

  // ---- GEMM2 accumulators: warp tile = 32 rows x 32 cols (32 regs) ----
  float acc2[2][4][4];
#pragma unroll
  for (int mt = 0; mt < 2; ++mt)
#pragma unroll
    for (int j = 0; j < 4; ++j)
#pragma unroll
      for (int q = 0; q < 4; ++q) acc2[mt][j][q] = 0.0f;

  // ---- chunk loop ----
  for (int kc = 0; kc < NCHUNK; ++kc) {
    // issue W2[kc] (single buffer, just freed) + W1[kc+1] (alt buffer)
    {
      const unsigned char* s2 = &g_w2img[kc][0];
      for (int i = tid; i < 2048; i += NTHREADS)
        cpa16(sm + SM_W2 + i * 16, s2 + (size_t)i * 16);
      if (kc + 1 < NCHUNK) {
        const unsigned char* s1 = &g_w1img[kc + 1][0];
        u32 d1 = sm + SM_W1 + (u32)((kc + 1) & 1) * W1BUFSZ;
        for (int i = tid; i < 512; i += NTHREADS)
          cpa16(d1 + i * 16, s1 + (size_t)i * 16);
      }
      CP_COMMIT();
    }

    // bias for convert
    float bv[4];
    {
      const int bb = kc * KC;
#pragma unroll
      for (int j = 0; j < 2; ++j) {
        int cc = bb + wc1 * 16 + j * 8 + 2 * tig;
        bv[j * 2]     = __ldg(b1 + cc);
        bv[j * 2 + 1] = __ldg(b1 + cc + 1);
      }
    }

    const u32 w1b = sm + SM_W1 + (u32)(kc & 1) * W1BUFSZ;

    // ---- GEMM1(kc): 1-pass, warp tile 16 x 16, 8 MMAs ----
    float acc1[2][4];
#pragma unroll
    for (int j = 0; j < 2; ++j)
#pragma unroll
      for (int q = 0; q < 4; ++q) acc1[j][q] = 0.0f;

#pragma unroll
    for (int kt = 0; kt < 4; ++kt) {
      const int k0 = kt * 16;
      u32 ax[4], bh[4];
      ldsm4(a_addr(sm + SM_X, wr1 * 16, k0, lr, lg), ax);
      ldsm4(b_addr(w1b, wc1 * 16, k0, lr, lg), bh);
      mma16816(acc1[0], ax, bh[0], bh[1]);
      mma16816(acc1[1], ax, bh[2], bh[3]);
    }

    // ---- convert: bias + relu -> h fp16 image ----
    {
      const int r0 = wr1 * 16 + gid;
#pragma unroll
      for (int j = 0; j < 2; ++j) {
        const int cc = wc1 * 16 + j * 8 + 2 * tig;
        float v0 = fmaxf(acc1[j][0] + bv[j * 2],     0.0f);
        float v1 = fmaxf(acc1[j][1] + bv[j * 2 + 1], 0.0f);
        float v2 = fmaxf(acc1[j][2] + bv[j * 2],     0.0f);
        float v3 = fmaxf(acc1[j][3] + bv[j * 2 + 1], 0.0f);
        *(u32*)(smem_raw + SM_H + swz(r0, cc))     = pack_h2(v0, v1);
        *(u32*)(smem_raw + SM_H + swz(r0 + 8, cc)) = pack_h2(v2, v3);
      }
    }

    CP_WAIT0();
    __syncthreads();          // h[kc] + W2[kc] (+W1[kc+1]) visible

    // ---- GEMM2(kc): 1-pass, warp tile 32 x 32, 32 MMAs ----
#pragma unroll
    for (int kt = 0; kt < 4; ++kt) {
      const int k0 = kt * 16;
      u32 ah[2][4];
      ldsm4(a_addr(sm + SM_H, 0,  k0, lr, lg), ah[0]);
      ldsm4(a_addr(sm + SM_H, 16, k0, lr, lg), ah[1]);
      u32 bf[2][4];
#pragma unroll
      for (int t = 0; t < 2; ++t)
        ldsm4(b_addr(sm + SM_W2, wid * 32 + t * 16, k0, lr, lg), bf[t]);
#pragma unroll
      for (int t = 0; t < 2; ++t) {
        mma16816(acc2[0][2*t],     ah[0], bf[t][0], bf[t][1]);
        mma16816(acc2[0][2*t + 1], ah[0], bf[t][2], bf[t][3]);
        mma16816(acc2[1][2*t],     ah[1], bf[t][0], bf[t][1]);
        mma16816(acc2[1][2*t + 1], ah[1], bf[t][2], bf[t][3]);
      }
    }
    __syncthreads();          // GEMM2 reads done before W2/h overwrite next iter
  }

  // ---- epilogue: + b2 (__ldg), store ----
#pragma unroll
  for (int mt = 0; mt < 2; ++mt) {
    const int r0 = row0 + mt * 16 + gid;
#pragma unroll
    for (int j = 0; j < 4; ++j) {
      const int c = wid * 32 + j * 8 + 2 * tig;
      const float bb0 = __ldg(b2 + c), bb1 = __ldg(b2 + c + 1);
      float2 va = make_float2(acc2[mt][j][0] + bb0, acc2[mt][j][1] + bb1);
      float2 vb = make_float2(acc2[mt][j][2] + bb0, acc2[mt][j][3] + bb1);
      *(float2*)(out + (size_t)r0 * EDIM + c)       = va;
      *(float2*)(out + (size_t)(r0 + 8) * EDIM + c) = vb;
    }
  }
}

// ============================ launch ========================================
extern "C" void kernel_launch(void* const* d_in, const int* in_sizes, int n_in,
                              void* d_out, int out_size) {
  (void)in_sizes; (void)n_in; (void)out_size;
  const float* seq = (const float*)d_in[0];
  const float* W1  = (const float*)d_in[1];
  const float* b1  = (const float*)d_in[2];
  const float* W2  = (const float*)d_in[3];
  const float* b2  = (const float*)d_in[4];

  cudaFuncSetAttribute(seqfc_main, cudaFuncAttributeMaxDynamicSharedMemorySize,
                       SMEM_TOTAL);

  const int prep_total = NCHUNK * KC * K1PAD + NCHUNK * EDIM * K1PAD;
  prep_kernel<<<(prep_total + 255) / 256, 256>>>(W1, W2);
  seqfc_main<<<B_TOTAL / MTILE, NTHREADS, SMEM_TOTAL>>>(seq, b1, b2, (float*)d_out);
}

// round 11
// speedup vs baseline: 2.6333x; 1.2324x over previous
#include <cuda_runtime.h>
#include <cuda_fp16.h>
#include <stdint.h>

// ---------------------------------------------------------------------------
// SeqFCEncoder via warp-level mma.sync (compute_103 base ISA).
// R11: weights pre-packed in MMA *fragment order* in gmem; loaded by LDG.128
//      directly to registers (no smem, no cp.async, no ldsm for weights).
//      Only X and h stay in smem (h double-buffered -> 1 bar/chunk).
//      Both GEMMs 1-pass fp16 (math identical to R10). MTILE=64, 2 CTAs/SM.
// ---------------------------------------------------------------------------

typedef unsigned int u32;
typedef unsigned long long u64;

#define B_TOTAL   262144
#define LSEQ      50
#define HDIM      1024
#define EDIM      256
#define MTILE     64
#define NTHREADS  256
#define KC        64
#define NCHUNK    (HDIM / KC)     // 16

// ---- smem layout (bytes, dynamic) ----
#define SM_X     0               // 8KB  X fp16 [64 m][64 k] SW128
#define SM_H0    8192            // 8KB  h buffer 0
#define SM_H1    16384           // 8KB  h buffer 1
#define SM_STAGE 24576           // 13.3KB fp32 staging (pre-loop only)
#define SMEM_TOTAL 38912         // -> 2 CTAs/SM (reg-bound anyway)

// ---- fragment-order weight images ----
// [kc][kt][nt][lane][r]: lane=(gid<<2)|tig; r0:(n=nt*16+gid,k=2tig,+1)
// r1:k+8  r2:n+8  r3:n+8,k+8   (exact mma16816 .row.col B-fragment layout)
__device__ __align__(16) u32 g_w1frag[NCHUNK][4][4][32][4];   // 128KB
__device__ __align__(16) u32 g_w2frag[NCHUNK][4][16][32][4];  // 512KB

// ============================ low-level helpers =============================
__device__ __forceinline__ u32 smem_u32_of(const void* p) {
  u32 a;
  asm("{ .reg .u64 t; cvta.to.shared.u64 t, %1; cvt.u32.u64 %0, t; }" : "=r"(a) : "l"(p));
  return a;
}
__device__ __forceinline__ u32 swz(int r, int k) {
  u32 off = ((u32)(r >> 3) << 10) | ((u32)(r & 7) << 7) | ((u32)k << 1);
  return off ^ ((off >> 3) & 0x70u);
}
__device__ __forceinline__ void ldsm4(u32 addr, u32 f[4]) {
  asm volatile("ldmatrix.sync.aligned.m8n8.x4.shared.b16 {%0,%1,%2,%3}, [%4];"
               : "=r"(f[0]), "=r"(f[1]), "=r"(f[2]), "=r"(f[3]) : "r"(addr));
}
__device__ __forceinline__ u32 a_addr(u32 img, int m0, int k0, int lr, int lg) {
  return img + swz(m0 + lr + ((lg & 1) << 3), k0 + ((lg >> 1) << 3));
}
__device__ __forceinline__ void mma16816(float c[4], const u32 a[4], u32 b0, u32 b1) {
  asm volatile(
    "mma.sync.aligned.m16n8k16.row.col.f32.f16.f16.f32 "
    "{%0,%1,%2,%3}, {%4,%5,%6,%7}, {%8,%9}, {%0,%1,%2,%3};"
    : "+f"(c[0]), "+f"(c[1]), "+f"(c[2]), "+f"(c[3])
    : "r"(a[0]), "r"(a[1]), "r"(a[2]), "r"(a[3]), "r"(b0), "r"(b1));
}

// ============================ threefry dropout ==============================
__device__ __forceinline__ u32 rotl32(u32 x, u32 r) { return __funnelshift_l(x, x, r); }
__device__ __forceinline__ void tf2x32(u32 x0, u32 x1, u32 &o0, u32 &o1) {
  const u32 ks0 = 0u, ks1 = 42u, ks2 = 0u ^ 42u ^ 0x1BD11BDAu;
  x0 += ks0; x1 += ks1;
#define TFR(r) { x0 += x1; x1 = rotl32(x1, r); x1 ^= x0; }
  TFR(13) TFR(15) TFR(26) TFR(6)
  x0 += ks1; x1 += ks2 + 1u;
  TFR(17) TFR(29) TFR(16) TFR(24)
  x0 += ks2; x1 += ks0 + 2u;
  TFR(13) TFR(15) TFR(26) TFR(6)
  x0 += ks0; x1 += ks1 + 3u;
  TFR(17) TFR(29) TFR(16) TFR(24)
  x0 += ks1; x1 += ks2 + 4u;
  TFR(13) TFR(15) TFR(26) TFR(6)
  x0 += ks2; x1 += ks0 + 5u;
#undef TFR
  o0 = x0; o1 = x1;
}
__device__ __forceinline__ bool drop_elem(u32 i) {   // validated rel_err 0.0 (R1)
  u32 o0, o1;
  tf2x32(0u, i, o0, o1);
  u32 bits = o0 ^ o1;
  float u = __uint_as_float((bits >> 9) | 0x3f800000u) - 1.0f;
  return u < 0.2f;
}

__device__ __forceinline__ u32 pack_h2(float a, float b) {
  return (u32)__half_as_ushort(__float2half_rn(a))
       | ((u32)__half_as_ushort(__float2half_rn(b)) << 16);
}

// ============================ prep kernel ===================================
// Pack W1/W2 (fp16-rounded) into per-lane MMA B-fragment order.
__global__ void prep_kernel(const float* __restrict__ W1,
                            const float* __restrict__ W2) {
  int idx = blockIdx.x * blockDim.x + threadIdx.x;
  const int NW1 = NCHUNK * 4 * 4 * 32 * 4;    // 32768 u32
  const int NW2 = NCHUNK * 4 * 16 * 32 * 4;   // 131072 u32
  if (idx < NW1) {
    int r = idx & 3, lane = (idx >> 2) & 31;
    int nt = (idx >> 7) & 3, kt = (idx >> 9) & 3, kc = idx >> 11;
    int gid = lane >> 2, tig = lane & 3;
    int n = nt * 16 + gid + ((r & 2) ? 8 : 0);
    int k = kt * 16 + 2 * tig + ((r & 1) ? 8 : 0);
    float w0 = (k     < LSEQ) ? W1[(size_t)k       * HDIM + kc * KC + n] : 0.0f;
    float w1 = (k + 1 < LSEQ) ? W1[(size_t)(k + 1) * HDIM + kc * KC + n] : 0.0f;
    g_w1frag[kc][kt][nt][lane][r] = pack_h2(w0, w1);
  } else if (idx < NW1 + NW2) {
    int j = idx - NW1;
    int r = j & 3, lane = (j >> 2) & 31;
    int nt = (j >> 7) & 15, kt = (j >> 11) & 3, kc = j >> 13;
    int gid = lane >> 2, tig = lane & 3;
    int n = nt * 16 + gid + ((r & 2) ? 8 : 0);
    int k = kc * KC + kt * 16 + 2 * tig + ((r & 1) ? 8 : 0);
    g_w2frag[kc][kt][nt][lane][r] =
        pack_h2(W2[(size_t)k * EDIM + n], W2[(size_t)(k + 1) * EDIM + n]);
  }
}

// ============================ main kernel ===================================
extern __shared__ __align__(1024) unsigned char smem_raw[];

__global__ void __launch_bounds__(NTHREADS, 2)
seqfc_main(const float* __restrict__ seq,
           const float* __restrict__ b1,
           const float* __restrict__ b2,
           float* __restrict__ out)
{
  const int tid  = threadIdx.x;
  const int wid  = tid >> 5;
  const int lane = tid & 31;
  const int lr   = lane & 7;
  const int lg   = lane >> 3;
  const int gid  = lane >> 2;
  const int tig  = lane & 3;
  const int wr   = wid >> 2;          // 2 row groups of 32
  const int wc   = wid & 3;           // 4 col groups
  const int row0 = blockIdx.x * MTILE;

  const u32 sm = smem_u32_of(smem_raw);

  // ---- X stage: fp32 staging -> mask+dropout -> fp16 SW128 image ----
  {
    float* xs = (float*)(smem_raw + SM_STAGE);     // stride 52
    const float* sp = seq + (size_t)row0 * LSEQ;
    for (int idx = tid; idx < MTILE * LSEQ; idx += NTHREADS) {
      int r = idx / LSEQ, k = idx - r * LSEQ;
      xs[r * 52 + k] = sp[idx];
    }
    __syncthreads();

    const int xrow = tid >> 2;          // 4 threads per row, 256 = 64*4
    const int q    = tid & 3;
    float xv[16];
#pragma unroll
    for (int i = 0; i < 16; ++i) {
      int k = q * 16 + i;
      xv[i] = (k < LSEQ) ? xs[xrow * 52 + k] : 0.0f;
    }
    int f = LSEQ;
#pragma unroll
    for (int i = 15; i >= 0; --i) {
      int k = q * 16 + i;
      if (k < LSEQ && xv[i] == -1.0f) f = k;
    }
    f = min(f, __shfl_xor_sync(0xffffffffu, f, 1));
    f = min(f, __shfl_xor_sync(0xffffffffu, f, 2));
    const u32 gb = (u32)(row0 + xrow) * (u32)LSEQ;
#pragma unroll
    for (int i = 0; i < 16; ++i) {
      int k = q * 16 + i;
      if (k < f && drop_elem(gb + (u32)k)) xv[i] = 0.0f;
    }
#pragma unroll
    for (int c = 0; c < 8; ++c) {
      u32 o = swz(xrow, q * 16 + 2 * c);
      *(u32*)(smem_raw + SM_X + o) = pack_h2(xv[2 * c], xv[2 * c + 1]);
    }
  }
  __syncthreads();            // X image ready

  // ---- GEMM2 accumulators: warp tile = 32 rows x 64 cols ----
  float acc2[2][8][4];
#pragma unroll
  for (int mt = 0; mt < 2; ++mt)
#pragma unroll
    for (int j = 0; j < 8; ++j)
#pragma unroll
      for (int q = 0; q < 4; ++q) acc2[mt][j][q] = 0.0f;

  // ---- chunk loop: ONE __syncthreads per chunk (h double-buffered) ----
  for (int kc = 0; kc < NCHUNK; ++kc) {
    // bias for this chunk's convert
    float bv[4];
    {
      const int bb = kc * KC;
#pragma unroll
      for (int j = 0; j < 2; ++j) {
        int cc = bb + wc * 16 + j * 8 + 2 * tig;
        bv[j * 2]     = __ldg(b1 + cc);
        bv[j * 2 + 1] = __ldg(b1 + cc + 1);
      }
    }

    // ---- GEMM1(kc): warp tile 32 x 16, W1 frags via LDG.128 ----
    float acc1[2][2][4];
#pragma unroll
    for (int mt = 0; mt < 2; ++mt)
#pragma unroll
      for (int j = 0; j < 2; ++j)
#pragma unroll
        for (int q = 0; q < 4; ++q) acc1[mt][j][q] = 0.0f;

#pragma unroll
    for (int kt = 0; kt < 4; ++kt) {
      const int k0 = kt * 16;
      u32 ax[2][4];
      ldsm4(a_addr(sm + SM_X, wr * 32,      k0, lr, lg), ax[0]);
      ldsm4(a_addr(sm + SM_X, wr * 32 + 16, k0, lr, lg), ax[1]);
      const uint4 bw = __ldg((const uint4*)g_w1frag[kc][kt][wc][lane]);
      mma16816(acc1[0][0], ax[0], bw.x, bw.y);
      mma16816(acc1[0][1], ax[0], bw.z, bw.w);
      mma16816(acc1[1][0], ax[1], bw.x, bw.y);
      mma16816(acc1[1][1], ax[1], bw.z, bw.w);
    }

    // ---- convert: bias + relu -> h fp16 image (buffer kc&1) ----
    const u32 hoff = (u32)(SM_H0 + ((kc & 1) << 13));
#pragma unroll
    for (int mt = 0; mt < 2; ++mt) {
      const int r0 = wr * 32 + mt * 16 + gid;
#pragma unroll
      for (int j = 0; j < 2; ++j) {
        const int cc = wc * 16 + j * 8 + 2 * tig;
        float v0 = fmaxf(acc1[mt][j][0] + bv[j * 2],     0.0f);
        float v1 = fmaxf(acc1[mt][j][1] + bv[j * 2 + 1], 0.0f);
        float v2 = fmaxf(acc1[mt][j][2] + bv[j * 2],     0.0f);
        float v3 = fmaxf(acc1[mt][j][3] + bv[j * 2 + 1], 0.0f);
        *(u32*)(smem_raw + hoff + swz(r0, cc))     = pack_h2(v0, v1);
        *(u32*)(smem_raw + hoff + swz(r0 + 8, cc)) = pack_h2(v2, v3);
      }
    }
    __syncthreads();          // h[kc] visible (also fences prior-buf reuse)

    // ---- GEMM2(kc): warp tile 32 x 64, W2 frags via LDG.128 ----
#pragma unroll
    for (int kt = 0; kt < 4; ++kt) {
      const int k0 = kt * 16;
      u32 ah[2][4];
      ldsm4(a_addr(sm + hoff, wr * 32,      k0, lr, lg), ah[0]);
      ldsm4(a_addr(sm + hoff, wr * 32 + 16, k0, lr, lg), ah[1]);
      uint4 bw[4];
#pragma unroll
      for (int t = 0; t < 4; ++t)
        bw[t] = __ldg((const uint4*)g_w2frag[kc][kt][wc * 4 + t][lane]);
#pragma unroll
      for (int t = 0; t < 4; ++t) {
        mma16816(acc2[0][2*t],     ah[0], bw[t].x, bw[t].y);
        mma16816(acc2[0][2*t + 1], ah[0], bw[t].z, bw[t].w);
        mma16816(acc2[1][2*t],     ah[1], bw[t].x, bw[t].y);
        mma16816(acc2[1][2*t + 1], ah[1], bw[t].z, bw[t].w);
      }
    }
    // no trailing bar: next chunk writes the other h buffer; the bar above
    // (next iteration) orders all G2 reads before that buffer's 2nd reuse.
  }

  // ---- epilogue: + b2 (__ldg), store ----
#pragma unroll
  for (int mt = 0; mt < 2; ++mt) {
    const int r0 = row0 + wr * 32 + mt * 16 + gid;
#pragma unroll
    for (int j = 0; j < 8; ++j) {
      const int c = wc * 64 + j * 8 + 2 * tig;
      const float bb0 = __ldg(b2 + c), bb1 = __ldg(b2 + c + 1);
      float2 va = make_float2(acc2[mt][j][0] + bb0, acc2[mt][j][1] + bb1);
      float2 vb = make_float2(acc2[mt][j][2] + bb0, acc2[mt][j][3] + bb1);
      *(float2*)(out + (size_t)r0 * EDIM + c)       = va;
      *(float2*)(out + (size_t)(r0 + 8) * EDIM + c) = vb;
    }
  }
}

// ============================ launch ========================================
extern "C" void kernel_launch(void* const* d_in, const int* in_sizes, int n_in,
                              void* d_out, int out_size) {
  (void)in_sizes; (void)n_in; (void)out_size;
  const float* seq = (const float*)d_in[0];
  const float* W1  = (const float*)d_in[1];
  const float* b1  = (const float*)d_in[2];
  const float* W2  = (const float*)d_in[3];
  const float* b2  = (const float*)d_in[4];

  cudaFuncSetAttribute(seqfc_main, cudaFuncAttributeMaxDynamicSharedMemorySize,
                       SMEM_TOTAL);

  const int prep_total = NCHUNK * 4 * 4 * 32 * 4 + NCHUNK * 4 * 16 * 32 * 4;
  prep_kernel<<<(prep_total + 255) / 256, 256>>>(W1, W2);
  seqfc_main<<<B_TOTAL / MTILE, NTHREADS, SMEM_TOTAL>>>(seq, b1, b2, (float*)d_out);
}